// round 14
// baseline (speedup 1.0000x reference)
#include <cuda_runtime.h>
#include <cuda_fp16.h>
#include <cstdint>

#define N_NODES 100000
#define N_EDGES 1600000
// IN_F = HID_F = 128, OUT_F = 64

#if defined(__CUDA_ARCH_FEAT_SM103_ALL)
#define HAS_TC 1
#else
#define HAS_TC 0
#endif

#define TOT_TILES ((N_NODES + 127) / 128)  // 782

// ---------------- scratch (device globals; no allocation allowed) ----------
__device__ int    g_deg[N_NODES];
__device__ int    g_off[N_NODES];
__device__ int    g_cur[N_NODES];
__device__ int    g_csr[N_EDGES];
__device__ int    g_bsum[128];
__device__ __half g_sp1s[(size_t)N_NODES * 128];   // feat @ W1_self (fp16)
__device__ __half g_sp1nH[(size_t)N_NODES * 128];  // feat @ W1_neigh (fp16)
__device__ __half g_h[(size_t)N_NODES * 128];      // relu(layer1) (fp16)
__device__ __half g_sp2s[(size_t)N_NODES * 64];    // h @ W2_self (fp16)
__device__ __half g_sp2nH[(size_t)N_NODES * 64];   // h @ W2_neigh (fp16)
// weights transposed [n][k], tf32 hi/lo pre-split (stored as fp32)
__device__ float  g_W1h[256 * 128];
__device__ float  g_W1l[256 * 128];
__device__ float  g_W2h[128 * 128];
__device__ float  g_W2l[128 * 128];

// ---------------- generic helpers -------------------------------------------
__device__ __forceinline__ uint32_t smem_u32(const void* p) {
    uint32_t a;
    asm("{ .reg .u64 t; cvta.to.shared.u64 t, %1; cvt.u32.u64 %0, t; }" : "=r"(a) : "l"(p));
    return a;
}
__device__ __forceinline__ float tf32r(float x) {
    uint32_t u;
    asm("cvt.rna.tf32.f32 %0, %1;" : "=r"(u) : "f"(x));
    return __uint_as_float(u);
}

#if HAS_TC
__device__ __forceinline__ uint32_t elect_one() {
    uint32_t p;
    asm volatile("{ .reg .pred p; elect.sync _|p, 0xFFFFFFFF; selp.b32 %0, 1, 0, p; }" : "=r"(p));
    return p;
}
#define MBAR_INIT(addr, cnt) \
    asm volatile("mbarrier.init.shared.b64 [%0], %1;" :: "r"(addr), "r"(cnt) : "memory")
__device__ __forceinline__ void mbar_wait(uint32_t addr, int phase) {
    asm volatile(
        "{\n\t.reg .pred P;\n\t"
        "WL_%=:\n\t"
        "mbarrier.try_wait.parity.acquire.cta.shared::cta.b64 P, [%0], %1, 0x989680;\n\t"
        "@P bra.uni WD_%=;\n\t"
        "bra.uni WL_%=;\n\t"
        "WD_%=:\n\t}"
        :: "r"(addr), "r"(phase) : "memory");
}
#define TC_ALLOC(ctrl, n) \
    asm volatile("tcgen05.alloc.cta_group::1.sync.aligned.shared::cta.b32 [%0], %1;" :: "r"(ctrl), "r"(n) : "memory")
#define TC_RELINQ() \
    asm volatile("tcgen05.relinquish_alloc_permit.cta_group::1.sync.aligned;")
#define TC_DEALLOC(t, n) \
    asm volatile("tcgen05.dealloc.cta_group::1.sync.aligned.b32 %0, %1;" :: "r"(t), "r"(n))
#define TC_COMMIT(mb) \
    asm volatile("tcgen05.commit.cta_group::1.mbarrier::arrive::one.shared::cluster.b64 [%0];" :: "r"(mb) : "memory")
#define TC_FENCE_AFTER()  asm volatile("tcgen05.fence::after_thread_sync;" ::: "memory")
#define TC_FENCE_BEFORE() asm volatile("tcgen05.fence::before_thread_sync;" ::: "memory")
#define TC_WAIT_LD()      asm volatile("tcgen05.wait::ld.sync.aligned;" ::: "memory")
#define FENCE_ASYNC()     asm volatile("fence.proxy.async.shared::cta;" ::: "memory")

__device__ __forceinline__ void tc_mma_tf32_ss(uint32_t d_tmem, uint64_t a_desc,
                                               uint64_t b_desc, uint32_t idesc, bool acc) {
    uint32_t en = acc ? 1u : 0u;
    asm volatile(
        "{\n\t.reg .pred p;\n\t"
        "setp.ne.u32 p, %4, 0;\n\t"
        "tcgen05.mma.cta_group::1.kind::tf32 [%0], %1, %2, %3, p;\n\t}"
        :: "r"(d_tmem), "l"(a_desc), "l"(b_desc), "r"(idesc), "r"(en) : "memory");
}

#define TC_LD_X32(r, a) \
    asm volatile( \
        "tcgen05.ld.sync.aligned.32x32b.x32.b32 " \
        "{%0,%1,%2,%3,%4,%5,%6,%7,%8,%9,%10,%11,%12,%13,%14,%15," \
        "%16,%17,%18,%19,%20,%21,%22,%23,%24,%25,%26,%27,%28,%29,%30,%31}, [%32];" \
        : "=r"((r)[0]),"=r"((r)[1]),"=r"((r)[2]),"=r"((r)[3]),"=r"((r)[4]),"=r"((r)[5]),"=r"((r)[6]),"=r"((r)[7]), \
          "=r"((r)[8]),"=r"((r)[9]),"=r"((r)[10]),"=r"((r)[11]),"=r"((r)[12]),"=r"((r)[13]),"=r"((r)[14]),"=r"((r)[15]), \
          "=r"((r)[16]),"=r"((r)[17]),"=r"((r)[18]),"=r"((r)[19]),"=r"((r)[20]),"=r"((r)[21]),"=r"((r)[22]),"=r"((r)[23]), \
          "=r"((r)[24]),"=r"((r)[25]),"=r"((r)[26]),"=r"((r)[27]),"=r"((r)[28]),"=r"((r)[29]),"=r"((r)[30]),"=r"((r)[31]) \
        : "r"(a))

// SW128 K-major descriptor: layout=2, version=1, SBO=64, LBO=1
__device__ __forceinline__ uint64_t mk_desc(uint32_t addr) {
    return ((uint64_t)2 << 61) | ((uint64_t)1 << 46) | ((uint64_t)64 << 32) |
           ((uint64_t)1 << 16) | (((uint64_t)addr >> 4) & 0x3FFF);
}

// idesc: dtype=F32, atype=TF32, btype=TF32, N=128, M=128
#define IDESC_TF32 ((1u << 4) | (2u << 7) | (2u << 10) | (16u << 17) | (8u << 24))
#endif  // HAS_TC

// ---------------- CSR build -------------------------------------------------
__global__ void k_zero_deg() {
    int i = blockIdx.x * blockDim.x + threadIdx.x;
    if (i < N_NODES) g_deg[i] = 0;
}

__global__ void k_hist(const int* __restrict__ dst) {
    int i = blockIdx.x * blockDim.x + threadIdx.x;
    if (i < N_EDGES) atomicAdd(&g_deg[dst[i]], 1);
}

__global__ void k_scan1() {
    __shared__ int s[1024];
    int tid = threadIdx.x;
    int i = blockIdx.x * 1024 + tid;
    int v = (i < N_NODES) ? g_deg[i] : 0;
    s[tid] = v;
    __syncthreads();
#pragma unroll
    for (int off = 1; off < 1024; off <<= 1) {
        int t = (tid >= off) ? s[tid - off] : 0;
        __syncthreads();
        s[tid] += t;
        __syncthreads();
    }
    if (i < N_NODES) g_off[i] = s[tid] - v;
    if (tid == 1023) g_bsum[blockIdx.x] = s[tid];
}

// fused: each block locally scans the 98 block sums, then applies
__global__ void k_scan3() {
    __shared__ int sbm[128];
    int tid = threadIdx.x;
    if (tid < 128) sbm[tid] = (tid < 98) ? g_bsum[tid] : 0;
    __syncthreads();
#pragma unroll
    for (int off = 1; off < 128; off <<= 1) {
        int t = 0;
        if (tid < 128 && tid >= off) t = sbm[tid - off];
        __syncthreads();
        if (tid < 128) sbm[tid] += t;
        __syncthreads();
    }
    int i = blockIdx.x * blockDim.x + tid;
    if (i < N_NODES) {
        int b = i >> 10;
        int add = (b > 0) ? sbm[b - 1] : 0;
        int o = g_off[i] + add;
        g_off[i] = o;
        g_cur[i] = o;
    }
}

__global__ void k_fill(const int* __restrict__ src, const int* __restrict__ dst) {
    int i = blockIdx.x * blockDim.x + threadIdx.x;
    if (i < N_EDGES) {
        int p = atomicAdd(&g_cur[dst[i]], 1);
        g_csr[p] = src[i];
    }
}

// pack both weight matrices transposed ([n][k]) with tf32 hi/lo pre-split
__global__ void k_pack(const float* __restrict__ W1s, const float* __restrict__ W1n,
                       const float* __restrict__ W2s, const float* __restrict__ W2n) {
    int i = blockIdx.x * blockDim.x + threadIdx.x;
    if (i < 256 * 128) {
        int n = i >> 7, k = i & 127;
        float v = (n < 128) ? W1s[k * 128 + n] : W1n[k * 128 + (n - 128)];
        float h = tf32r(v);
        g_W1h[i] = h;
        g_W1l[i] = tf32r(v - h);
    } else if (i < 256 * 128 + 128 * 128) {
        int j = i - 256 * 128;
        int n = j >> 7, k = j & 127;
        float v = (n < 64) ? W2s[k * 64 + n] : W2n[k * 64 + (n - 64)];
        float h = tf32r(v);
        g_W2h[j] = h;
        g_W2l[j] = tf32r(v - h);
    }
}

// ---------------- aggregation (warp per destination node) -------------------
// layer1: g_h[v] = relu(sp1s[v] + mean_u sp1nH[u] + b1)
// 4 edges per main iteration (2 independent LDG.128 in flight per lane).
__global__ void k_agg1(const float* __restrict__ b1) {
    int w = (blockIdx.x * blockDim.x + threadIdx.x) >> 5;
    int lane = threadIdx.x & 31;
    if (w >= N_NODES) return;
    int beg = g_off[w];
    int d = g_deg[w];
    int end = beg + d;
    const int colb = (lane & 15) * 8;
    const int half_id = lane >> 4;  // 0 or 1

    float acc[8];
#pragma unroll
    for (int j = 0; j < 8; j++) acc[j] = 0.f;

    int e = beg;
    for (; e + 3 < end; e += 4) {
        int s0 = g_csr[e + half_id];
        int s1 = g_csr[e + 2 + half_id];
        uint4 r0 = *(const uint4*)(g_sp1nH + (size_t)s0 * 128 + colb);
        uint4 r1 = *(const uint4*)(g_sp1nH + (size_t)s1 * 128 + colb);
#pragma unroll
        for (int q = 0; q < 4; q++) {
            uint32_t u0 = (&r0.x)[q];
            uint32_t u1 = (&r1.x)[q];
            float2 f0 = __half22float2(*(__half2*)&u0);
            float2 f1 = __half22float2(*(__half2*)&u1);
            acc[q * 2 + 0] += f0.x + f1.x;
            acc[q * 2 + 1] += f0.y + f1.y;
        }
    }
    for (; e + 1 < end; e += 2) {
        int s0 = g_csr[e + half_id];
        uint4 r0 = *(const uint4*)(g_sp1nH + (size_t)s0 * 128 + colb);
#pragma unroll
        for (int q = 0; q < 4; q++) {
            uint32_t u0 = (&r0.x)[q];
            float2 f0 = __half22float2(*(__half2*)&u0);
            acc[q * 2 + 0] += f0.x;
            acc[q * 2 + 1] += f0.y;
        }
    }
    if (e < end && half_id == 0) {  // odd tail
        int s0 = g_csr[e];
        uint4 r0 = *(const uint4*)(g_sp1nH + (size_t)s0 * 128 + colb);
#pragma unroll
        for (int q = 0; q < 4; q++) {
            uint32_t u0 = (&r0.x)[q];
            float2 f0 = __half22float2(*(__half2*)&u0);
            acc[q * 2 + 0] += f0.x;
            acc[q * 2 + 1] += f0.y;
        }
    }
#pragma unroll
    for (int j = 0; j < 8; j++) acc[j] += __shfl_xor_sync(0xFFFFFFFF, acc[j], 16);

    if (lane < 16) {
        float inv = (d > 0) ? 1.0f / (float)d : 0.0f;
        uint4 sr = *(const uint4*)(g_sp1s + (size_t)w * 128 + colb);
        float4 bb0 = *(const float4*)(b1 + colb);
        float4 bb1 = *(const float4*)(b1 + colb + 4);
        float bv[8] = {bb0.x, bb0.y, bb0.z, bb0.w, bb1.x, bb1.y, bb1.z, bb1.w};
        uint32_t outp[4];
#pragma unroll
        for (int q = 0; q < 4; q++) {
            uint32_t u = (&sr.x)[q];
            float2 s2 = __half22float2(*(__half2*)&u);
            float o0 = fmaxf(s2.x + acc[q * 2 + 0] * inv + bv[q * 2 + 0], 0.f);
            float o1 = fmaxf(s2.y + acc[q * 2 + 1] * inv + bv[q * 2 + 1], 0.f);
            __half2 hh = __floats2half2_rn(o0, o1);
            outp[q] = *(uint32_t*)&hh;
        }
        *(uint4*)(g_h + (size_t)w * 128 + colb) = make_uint4(outp[0], outp[1], outp[2], outp[3]);
    }
}

// layer2: out[v][c] = sp2s[v][c] + mean_u sp2nH[u][c] + b2[c]
// 8 edges per main iteration (2 independent LDG.128 in flight per lane).
__global__ void k_agg2(const float* __restrict__ b2, float* __restrict__ out) {
    int w = (blockIdx.x * blockDim.x + threadIdx.x) >> 5;
    int lane = threadIdx.x & 31;
    if (w >= N_NODES) return;
    int beg = g_off[w];
    int d = g_deg[w];
    int end = beg + d;
    const int colb = (lane & 7) * 8;
    const int sub = lane >> 3;  // 0..3

    float acc[8];
#pragma unroll
    for (int j = 0; j < 8; j++) acc[j] = 0.f;

    int e = beg;
    for (; e + 7 < end; e += 8) {
        int s0 = g_csr[e + sub];
        int s1 = g_csr[e + 4 + sub];
        uint4 r0 = *(const uint4*)(g_sp2nH + (size_t)s0 * 64 + colb);
        uint4 r1 = *(const uint4*)(g_sp2nH + (size_t)s1 * 64 + colb);
#pragma unroll
        for (int q = 0; q < 4; q++) {
            uint32_t u0 = (&r0.x)[q];
            uint32_t u1 = (&r1.x)[q];
            float2 f0 = __half22float2(*(__half2*)&u0);
            float2 f1 = __half22float2(*(__half2*)&u1);
            acc[q * 2 + 0] += f0.x + f1.x;
            acc[q * 2 + 1] += f0.y + f1.y;
        }
    }
    for (; e < end; e += 4) {
        int idx = e + sub;
        if (idx < end) {
            int s = g_csr[idx];
            uint4 r = *(const uint4*)(g_sp2nH + (size_t)s * 64 + colb);
#pragma unroll
            for (int q = 0; q < 4; q++) {
                uint32_t u = (&r.x)[q];
                float2 f = __half22float2(*(__half2*)&u);
                acc[q * 2 + 0] += f.x;
                acc[q * 2 + 1] += f.y;
            }
        }
    }
#pragma unroll
    for (int j = 0; j < 8; j++) {
        acc[j] += __shfl_xor_sync(0xFFFFFFFF, acc[j], 8);
        acc[j] += __shfl_xor_sync(0xFFFFFFFF, acc[j], 16);
    }

    if (lane < 8) {
        float inv = (d > 0) ? 1.0f / (float)d : 0.0f;
        uint4 sr = *(const uint4*)(g_sp2s + (size_t)w * 64 + colb);
        float4 bb0 = *(const float4*)(b2 + colb);
        float4 bb1 = *(const float4*)(b2 + colb + 4);
        float bv[8] = {bb0.x, bb0.y, bb0.z, bb0.w, bb1.x, bb1.y, bb1.z, bb1.w};
        float o[8];
#pragma unroll
        for (int q = 0; q < 4; q++) {
            uint32_t u = (&sr.x)[q];
            float2 s2 = __half22float2(*(__half2*)&u);
            o[q * 2 + 0] = s2.x + acc[q * 2 + 0] * inv + bv[q * 2 + 0];
            o[q * 2 + 1] = s2.y + acc[q * 2 + 1] * inv + bv[q * 2 + 1];
        }
        *(float4*)(out + (size_t)w * 64 + colb)     = make_float4(o[0], o[1], o[2], o[3]);
        *(float4*)(out + (size_t)w * 64 + colb + 4) = make_float4(o[4], o[5], o[6], o[7]);
    }
}

// ---------------- GEMM (tcgen05 on sm_103a; naive fallback otherwise) --------
// A is fp16-precision (exact in tf32, single tile). LAYER 1 reads fp32 feat and
// rounds through fp16 inline; LAYER 2 reads fp16 g_h. B tf32 hi/lo pre-split.
// LAYER 1 (NT=2): [sp1s | sp1nH](fp16) = round16(feat) @ W1^T
// LAYER 2 (NT=1): [sp2s | sp2nH](fp16) = g_h @ W2^T
#define GEMM1_SMEM (1024 + 5 * 16384)
#define GEMM2_SMEM (1024 + 3 * 16384)

template <int NT, int LAYER>
__global__ __launch_bounds__(256) void k_gemm(const float* __restrict__ A0) {
    extern __shared__ __align__(1024) char smem[];
    const int tid = threadIdx.x;
    const int row0 = blockIdx.x * 128;
    const float* Wbh = (LAYER == 1) ? g_W1h : g_W2h;
    const float* Wbl = (LAYER == 1) ? g_W1l : g_W2l;

#if HAS_TC
    const uint32_t sb = smem_u32(smem);
    const uint32_t ctrl = sb;
    const uint32_t mb = sb + 16;
    const uint32_t smA = sb + 1024;
    uint32_t smBh[2], smBl[2];
    smBh[0] = smA + 16384;
    smBl[0] = smBh[0] + 16384;
    smBh[1] = smBl[0] + 16384;
    smBl[1] = smBh[1] + 16384;

    const int wid = tid >> 5;
    const int lane = tid & 31;

    if (wid == 0) {
        TC_ALLOC(ctrl, NT * 128);
        TC_RELINQ();
    }
    if (tid == 0) MBAR_INIT(mb, 1);
    __syncthreads();
    uint32_t tmem;
    asm volatile("ld.shared.b32 %0, [%1];" : "=r"(tmem) : "r"(ctrl));

    int ph = 0;
    for (int c = 0; c < 4; c++) {
        if (c > 0) { mbar_wait(mb, ph); ph ^= 1; }
        const int k0 = c * 32;

#pragma unroll
        for (int i = 0; i < 4; i++) {
            int slot = tid * 4 + i;       // 0..1023
            int rw = slot >> 3;           // 0..127
            int c16 = slot & 7;           // 0..7
            uint32_t bo = rw * 128 + c16 * 16;
            uint32_t sw = bo ^ ((bo >> 3) & 0x70);
            int r = row0 + rw;
            // A: fp16-precision values as fp32 (exact in tf32), single tile
            float4 av = make_float4(0.f, 0.f, 0.f, 0.f);
            if (r < N_NODES) {
                if (LAYER == 1) {
                    // inline fp32 -> fp16(rn) -> fp32: bit-identical to cvt+fp16 load
                    float4 fv = *(const float4*)(A0 + (size_t)r * 128 + k0 + c16 * 4);
                    __half2 h0 = __floats2half2_rn(fv.x, fv.y);
                    __half2 h1 = __floats2half2_rn(fv.z, fv.w);
                    float2 f0 = __half22float2(h0);
                    float2 f1 = __half22float2(h1);
                    av = make_float4(f0.x, f0.y, f1.x, f1.y);
                } else {
                    uint2 hv = *(const uint2*)(g_h + (size_t)r * 128 + k0 + c16 * 4);
                    float2 f0 = __half22float2(*(__half2*)&hv.x);
                    float2 f1 = __half22float2(*(__half2*)&hv.y);
                    av = make_float4(f0.x, f0.y, f1.x, f1.y);
                }
            }
            *(float4*)(smem + (smA - sb) + sw) = av;
            // B tiles (pre-split tf32 hi/lo, straight 16B copies)
#pragma unroll
            for (int nt = 0; nt < NT; nt++) {
                size_t src = (size_t)(nt * 128 + rw) * 128 + k0 + c16 * 4;
                *(float4*)(smem + (smBh[nt] - sb) + sw) = *(const float4*)(Wbh + src);
                *(float4*)(smem + (smBl[nt] - sb) + sw) = *(const float4*)(Wbl + src);
            }
        }
        FENCE_ASYNC();
        __syncthreads();
        if (wid == 0) {
            if (elect_one()) {
                uint64_t ad = mk_desc(smA);
#pragma unroll
                for (int nt = 0; nt < NT; nt++) {
                    uint64_t bdh = mk_desc(smBh[nt]), bdl = mk_desc(smBl[nt]);
                    uint32_t dt = tmem + nt * 128;
#pragma unroll
                    for (int s = 0; s < 4; s++) {
                        tc_mma_tf32_ss(dt, ad + s * 2, bdh + s * 2, IDESC_TF32, !(c == 0 && s == 0));
                        tc_mma_tf32_ss(dt, ad + s * 2, bdl + s * 2, IDESC_TF32, true);
                    }
                }
                TC_COMMIT(mb);
            }
        }
    }
    mbar_wait(mb, ph);
    TC_FENCE_AFTER();

    // epilogue: warps 0..3 each cover 32 M-rows; paired tcgen05.ld, one wait per 64 cols
    if (wid < 4) {
        int r = row0 + wid * 32 + lane;
        const int NCOL = (LAYER == 1) ? 128 : 64;  // per half
        __half* dst_s = (LAYER == 1) ? g_sp1s : g_sp2s;
        __half* dst_n = (LAYER == 1) ? g_sp1nH : g_sp2nH;
#pragma unroll
        for (int half = 0; half < 2; half++) {
            __half* D = half ? dst_n : dst_s;
            int tb = half * NCOL;
#pragma unroll
            for (int off = 0; off < NCOL; off += 64) {
                uint32_t dr0[32], dr1[32];
                TC_LD_X32(dr0, tmem + tb + off);
                TC_LD_X32(dr1, tmem + tb + off + 32);
                TC_WAIT_LD();
                if (r < N_NODES) {
                    uint32_t pk[32];
#pragma unroll
                    for (int q = 0; q < 16; q++) {
                        __half2 h0 = __floats2half2_rn(__uint_as_float(dr0[2 * q]),
                                                       __uint_as_float(dr0[2 * q + 1]));
                        __half2 h1 = __floats2half2_rn(__uint_as_float(dr1[2 * q]),
                                                       __uint_as_float(dr1[2 * q + 1]));
                        pk[q] = *(uint32_t*)&h0;
                        pk[16 + q] = *(uint32_t*)&h1;
                    }
#pragma unroll
                    for (int q = 0; q < 8; q++)
                        *(uint4*)(D + (size_t)r * NCOL + off + q * 8) =
                            make_uint4(pk[q * 4], pk[q * 4 + 1], pk[q * 4 + 2], pk[q * 4 + 3]);
                }
            }
        }
        TC_FENCE_BEFORE();
    }
    __syncthreads();
    if (wid == 0) TC_DEALLOC(tmem, NT * 128);

#else  // ---------------- naive fallback (non-sm_103a pass; never runs on GB300)
    for (int e = tid; e < 128 * NT * 128; e += 256) {
        int rr = e / (NT * 128);
        int cc = e % (NT * 128);
        int r = row0 + rr;
        if (r >= N_NODES) continue;
        float s = 0.f;
        for (int k = 0; k < 128; k++) {
            float a;
            if (LAYER == 1)
                a = __half2float(__float2half_rn(A0[(size_t)r * 128 + k]));
            else
                a = __half2float(g_h[(size_t)r * 128 + k]);
            s += a * (Wbh[(size_t)cc * 128 + k] + Wbl[(size_t)cc * 128 + k]);
        }
        if (LAYER == 1) {
            if (cc < 128) g_sp1s[(size_t)r * 128 + cc] = __float2half_rn(s);
            else          g_sp1nH[(size_t)r * 128 + (cc - 128)] = __float2half_rn(s);
        } else {
            if (cc < 64) g_sp2s[(size_t)r * 64 + cc] = __float2half_rn(s);
            else         g_sp2nH[(size_t)r * 64 + (cc - 64)] = __float2half_rn(s);
        }
    }
#endif
}

// ---------------- launch -----------------------------------------------------
extern "C" void kernel_launch(void* const* d_in, const int* in_sizes, int n_in,
                              void* d_out, int out_size) {
    const float* feat = (const float*)d_in[0];
    const int*   esrc = (const int*)d_in[1];
    const int*   edst = (const int*)d_in[2];
    const float* W1s  = (const float*)d_in[3];
    const float* W1n  = (const float*)d_in[4];
    const float* b1   = (const float*)d_in[5];
    const float* W2s  = (const float*)d_in[6];
    const float* W2n  = (const float*)d_in[7];
    const float* b2   = (const float*)d_in[8];
    float* out = (float*)d_out;

    static cudaStream_t s1 = nullptr;
    static cudaEvent_t e0 = nullptr, e1 = nullptr;
    if (!s1) {
        cudaStreamCreateWithFlags(&s1, cudaStreamNonBlocking);
        cudaEventCreateWithFlags(&e0, cudaEventDisableTiming);
        cudaEventCreateWithFlags(&e1, cudaEventDisableTiming);
    }

    cudaFuncSetAttribute(k_gemm<2, 1>, cudaFuncAttributeMaxDynamicSharedMemorySize, GEMM1_SMEM);
    cudaFuncSetAttribute(k_gemm<1, 2>, cudaFuncAttributeMaxDynamicSharedMemorySize, GEMM2_SMEM);

    const int TB = 256;

    // ---- fork: stream s1 does pack + layer-1 projection GEMM (graph-independent)
    cudaEventRecord(e0, 0);
    cudaStreamWaitEvent(s1, e0, 0);
    k_pack<<<(256 * 128 + 128 * 128 + TB - 1) / TB, TB, 0, s1>>>(W1s, W1n, W2s, W2n);
    k_gemm<2, 1><<<TOT_TILES, 256, GEMM1_SMEM, s1>>>(feat);
    cudaEventRecord(e1, s1);

    // ---- default stream: CSR build
    k_zero_deg<<<(N_NODES + TB - 1) / TB, TB>>>();
    k_hist<<<(N_EDGES + TB - 1) / TB, TB>>>(edst);
    k_scan1<<<(N_NODES + 1023) / 1024, 1024>>>();
    k_scan3<<<(N_NODES + TB - 1) / TB, TB>>>();
    k_fill<<<(N_EDGES + TB - 1) / TB, TB>>>(esrc, edst);

    // ---- join
    cudaStreamWaitEvent(0, e1, 0);

    // layer 1 aggregate (+self+bias+relu), layer 2 projection, layer 2 aggregate
    k_agg1<<<(N_NODES * 32 + TB - 1) / TB, TB>>>(b1);
    k_gemm<1, 2><<<TOT_TILES, 256, GEMM2_SMEM>>>(nullptr);
    k_agg2<<<(N_NODES * 32 + TB - 1) / TB, TB>>>(b2, out);
}

// round 15
// speedup vs baseline: 1.1036x; 1.1036x over previous
#include <cuda_runtime.h>
#include <cuda_fp16.h>
#include <cstdint>

#define N_NODES 100000
#define N_EDGES 1600000
// IN_F = HID_F = 128, OUT_F = 64

#if defined(__CUDA_ARCH_FEAT_SM103_ALL)
#define HAS_TC 1
#else
#define HAS_TC 0
#endif

#define TOT_TILES ((N_NODES + 127) / 128)  // 782

// ---------------- scratch (device globals; no allocation allowed) ----------
__device__ int    g_deg[N_NODES];
__device__ int    g_off[N_NODES];
__device__ int    g_cur[N_NODES];
__device__ int    g_csr[N_EDGES];
__device__ int    g_bsum[128];
__device__ __half g_sp1s[(size_t)N_NODES * 128];   // feat @ W1_self (fp16)
__device__ __half g_sp1nH[(size_t)N_NODES * 128];  // feat @ W1_neigh (fp16)
__device__ __half g_h[(size_t)N_NODES * 128];      // relu(layer1) (fp16)
__device__ __half g_sp2s[(size_t)N_NODES * 64];    // h @ W2_self (fp16)
__device__ __half g_sp2nH[(size_t)N_NODES * 64];   // h @ W2_neigh (fp16)
__device__ float  g_W1cat[256 * 128];              // B^T layer1: [n][k], n<128 self, else neigh
__device__ float  g_W2cat[128 * 128];              // B^T layer2: [n][k], n<64 self, else neigh

// ---------------- generic helpers -------------------------------------------
__device__ __forceinline__ uint32_t smem_u32(const void* p) {
    uint32_t a;
    asm("{ .reg .u64 t; cvta.to.shared.u64 t, %1; cvt.u32.u64 %0, t; }" : "=r"(a) : "l"(p));
    return a;
}
__device__ __forceinline__ float tf32r(float x) {
    uint32_t u;
    asm("cvt.rna.tf32.f32 %0, %1;" : "=r"(u) : "f"(x));
    return __uint_as_float(u);
}

#if HAS_TC
__device__ __forceinline__ uint32_t elect_one() {
    uint32_t p;
    asm volatile("{ .reg .pred p; elect.sync _|p, 0xFFFFFFFF; selp.b32 %0, 1, 0, p; }" : "=r"(p));
    return p;
}
#define MBAR_INIT(addr, cnt) \
    asm volatile("mbarrier.init.shared.b64 [%0], %1;" :: "r"(addr), "r"(cnt) : "memory")
__device__ __forceinline__ void mbar_wait(uint32_t addr, int phase) {
    asm volatile(
        "{\n\t.reg .pred P;\n\t"
        "WL_%=:\n\t"
        "mbarrier.try_wait.parity.acquire.cta.shared::cta.b64 P, [%0], %1, 0x989680;\n\t"
        "@P bra.uni WD_%=;\n\t"
        "bra.uni WL_%=;\n\t"
        "WD_%=:\n\t}"
        :: "r"(addr), "r"(phase) : "memory");
}
#define TC_ALLOC(ctrl, n) \
    asm volatile("tcgen05.alloc.cta_group::1.sync.aligned.shared::cta.b32 [%0], %1;" :: "r"(ctrl), "r"(n) : "memory")
#define TC_RELINQ() \
    asm volatile("tcgen05.relinquish_alloc_permit.cta_group::1.sync.aligned;")
#define TC_DEALLOC(t, n) \
    asm volatile("tcgen05.dealloc.cta_group::1.sync.aligned.b32 %0, %1;" :: "r"(t), "r"(n))
#define TC_COMMIT(mb) \
    asm volatile("tcgen05.commit.cta_group::1.mbarrier::arrive::one.shared::cluster.b64 [%0];" :: "r"(mb) : "memory")
#define TC_FENCE_AFTER()  asm volatile("tcgen05.fence::after_thread_sync;" ::: "memory")
#define TC_FENCE_BEFORE() asm volatile("tcgen05.fence::before_thread_sync;" ::: "memory")
#define TC_WAIT_LD()      asm volatile("tcgen05.wait::ld.sync.aligned;" ::: "memory")
#define FENCE_ASYNC()     asm volatile("fence.proxy.async.shared::cta;" ::: "memory")

__device__ __forceinline__ void tc_mma_tf32_ss(uint32_t d_tmem, uint64_t a_desc,
                                               uint64_t b_desc, uint32_t idesc, bool acc) {
    uint32_t en = acc ? 1u : 0u;
    asm volatile(
        "{\n\t.reg .pred p;\n\t"
        "setp.ne.u32 p, %4, 0;\n\t"
        "tcgen05.mma.cta_group::1.kind::tf32 [%0], %1, %2, %3, p;\n\t}"
        :: "r"(d_tmem), "l"(a_desc), "l"(b_desc), "r"(idesc), "r"(en) : "memory");
}

#define TC_LD_X32(r, a) \
    asm volatile( \
        "tcgen05.ld.sync.aligned.32x32b.x32.b32 " \
        "{%0,%1,%2,%3,%4,%5,%6,%7,%8,%9,%10,%11,%12,%13,%14,%15," \
        "%16,%17,%18,%19,%20,%21,%22,%23,%24,%25,%26,%27,%28,%29,%30,%31}, [%32];" \
        : "=r"((r)[0]),"=r"((r)[1]),"=r"((r)[2]),"=r"((r)[3]),"=r"((r)[4]),"=r"((r)[5]),"=r"((r)[6]),"=r"((r)[7]), \
          "=r"((r)[8]),"=r"((r)[9]),"=r"((r)[10]),"=r"((r)[11]),"=r"((r)[12]),"=r"((r)[13]),"=r"((r)[14]),"=r"((r)[15]), \
          "=r"((r)[16]),"=r"((r)[17]),"=r"((r)[18]),"=r"((r)[19]),"=r"((r)[20]),"=r"((r)[21]),"=r"((r)[22]),"=r"((r)[23]), \
          "=r"((r)[24]),"=r"((r)[25]),"=r"((r)[26]),"=r"((r)[27]),"=r"((r)[28]),"=r"((r)[29]),"=r"((r)[30]),"=r"((r)[31]) \
        : "r"(a))

// SW128 K-major descriptor: layout=2, version=1, SBO=64, LBO=1
__device__ __forceinline__ uint64_t mk_desc(uint32_t addr) {
    return ((uint64_t)2 << 61) | ((uint64_t)1 << 46) | ((uint64_t)64 << 32) |
           ((uint64_t)1 << 16) | (((uint64_t)addr >> 4) & 0x3FFF);
}

// idesc: dtype=F32, atype=TF32, btype=TF32, N=128, M=128
#define IDESC_TF32 ((1u << 4) | (2u << 7) | (2u << 10) | (16u << 17) | (8u << 24))
#endif  // HAS_TC

// ---------------- CSR build -------------------------------------------------
__global__ void k_zero_deg() {
    int i = blockIdx.x * blockDim.x + threadIdx.x;
    if (i < N_NODES) g_deg[i] = 0;
}

__global__ void k_hist(const int* __restrict__ dst) {
    int i = blockIdx.x * blockDim.x + threadIdx.x;
    if (i < N_EDGES) atomicAdd(&g_deg[dst[i]], 1);
}

__global__ void k_scan1() {
    __shared__ int s[1024];
    int tid = threadIdx.x;
    int i = blockIdx.x * 1024 + tid;
    int v = (i < N_NODES) ? g_deg[i] : 0;
    s[tid] = v;
    __syncthreads();
#pragma unroll
    for (int off = 1; off < 1024; off <<= 1) {
        int t = (tid >= off) ? s[tid - off] : 0;
        __syncthreads();
        s[tid] += t;
        __syncthreads();
    }
    if (i < N_NODES) g_off[i] = s[tid] - v;
    if (tid == 1023) g_bsum[blockIdx.x] = s[tid];
}

// fused: each block locally scans the 98 block sums, then applies
__global__ void k_scan3() {
    __shared__ int sbm[128];
    int tid = threadIdx.x;
    if (tid < 128) sbm[tid] = (tid < 98) ? g_bsum[tid] : 0;
    __syncthreads();
#pragma unroll
    for (int off = 1; off < 128; off <<= 1) {
        int t = 0;
        if (tid < 128 && tid >= off) t = sbm[tid - off];
        __syncthreads();
        if (tid < 128) sbm[tid] += t;
        __syncthreads();
    }
    int i = blockIdx.x * blockDim.x + tid;
    if (i < N_NODES) {
        int b = i >> 10;
        int add = (b > 0) ? sbm[b - 1] : 0;
        int o = g_off[i] + add;
        g_off[i] = o;
        g_cur[i] = o;
    }
}

__global__ void k_fill(const int* __restrict__ src, const int* __restrict__ dst) {
    int i = blockIdx.x * blockDim.x + threadIdx.x;
    if (i < N_EDGES) {
        int p = atomicAdd(&g_cur[dst[i]], 1);
        g_csr[p] = src[i];
    }
}

// pack both weight matrices transposed ([n][k])
__global__ void k_pack(const float* __restrict__ W1s, const float* __restrict__ W1n,
                       const float* __restrict__ W2s, const float* __restrict__ W2n) {
    int i = blockIdx.x * blockDim.x + threadIdx.x;
    if (i < 256 * 128) {
        int n = i >> 7, k = i & 127;
        g_W1cat[i] = (n < 128) ? W1s[k * 128 + n] : W1n[k * 128 + (n - 128)];
    } else if (i < 256 * 128 + 128 * 128) {
        int j = i - 256 * 128;
        int n = j >> 7, k = j & 127;
        g_W2cat[j] = (n < 64) ? W2s[k * 64 + n] : W2n[k * 64 + (n - 64)];
    }
}

// ---------------- aggregation (warp per destination node) -------------------
// layer1: g_h[v] = relu(sp1s[v] + mean_u sp1nH[u] + b1)
// 4 edges per main iteration (2 independent LDG.128 in flight per lane).
__global__ void k_agg1(const float* __restrict__ b1) {
    int w = (blockIdx.x * blockDim.x + threadIdx.x) >> 5;
    int lane = threadIdx.x & 31;
    if (w >= N_NODES) return;
    int beg = g_off[w];
    int d = g_deg[w];
    int end = beg + d;
    const int colb = (lane & 15) * 8;
    const int half_id = lane >> 4;  // 0 or 1

    float acc[8];
#pragma unroll
    for (int j = 0; j < 8; j++) acc[j] = 0.f;

    int e = beg;
    for (; e + 3 < end; e += 4) {
        int s0 = g_csr[e + half_id];
        int s1 = g_csr[e + 2 + half_id];
        uint4 r0 = *(const uint4*)(g_sp1nH + (size_t)s0 * 128 + colb);
        uint4 r1 = *(const uint4*)(g_sp1nH + (size_t)s1 * 128 + colb);
#pragma unroll
        for (int q = 0; q < 4; q++) {
            uint32_t u0 = (&r0.x)[q];
            uint32_t u1 = (&r1.x)[q];
            float2 f0 = __half22float2(*(__half2*)&u0);
            float2 f1 = __half22float2(*(__half2*)&u1);
            acc[q * 2 + 0] += f0.x + f1.x;
            acc[q * 2 + 1] += f0.y + f1.y;
        }
    }
    for (; e + 1 < end; e += 2) {
        int s0 = g_csr[e + half_id];
        uint4 r0 = *(const uint4*)(g_sp1nH + (size_t)s0 * 128 + colb);
#pragma unroll
        for (int q = 0; q < 4; q++) {
            uint32_t u0 = (&r0.x)[q];
            float2 f0 = __half22float2(*(__half2*)&u0);
            acc[q * 2 + 0] += f0.x;
            acc[q * 2 + 1] += f0.y;
        }
    }
    if (e < end && half_id == 0) {  // odd tail
        int s0 = g_csr[e];
        uint4 r0 = *(const uint4*)(g_sp1nH + (size_t)s0 * 128 + colb);
#pragma unroll
        for (int q = 0; q < 4; q++) {
            uint32_t u0 = (&r0.x)[q];
            float2 f0 = __half22float2(*(__half2*)&u0);
            acc[q * 2 + 0] += f0.x;
            acc[q * 2 + 1] += f0.y;
        }
    }
#pragma unroll
    for (int j = 0; j < 8; j++) acc[j] += __shfl_xor_sync(0xFFFFFFFF, acc[j], 16);

    if (lane < 16) {
        float inv = (d > 0) ? 1.0f / (float)d : 0.0f;
        uint4 sr = *(const uint4*)(g_sp1s + (size_t)w * 128 + colb);
        float4 bb0 = *(const float4*)(b1 + colb);
        float4 bb1 = *(const float4*)(b1 + colb + 4);
        float bv[8] = {bb0.x, bb0.y, bb0.z, bb0.w, bb1.x, bb1.y, bb1.z, bb1.w};
        uint32_t outp[4];
#pragma unroll
        for (int q = 0; q < 4; q++) {
            uint32_t u = (&sr.x)[q];
            float2 s2 = __half22float2(*(__half2*)&u);
            float o0 = fmaxf(s2.x + acc[q * 2 + 0] * inv + bv[q * 2 + 0], 0.f);
            float o1 = fmaxf(s2.y + acc[q * 2 + 1] * inv + bv[q * 2 + 1], 0.f);
            __half2 hh = __floats2half2_rn(o0, o1);
            outp[q] = *(uint32_t*)&hh;
        }
        *(uint4*)(g_h + (size_t)w * 128 + colb) = make_uint4(outp[0], outp[1], outp[2], outp[3]);
    }
}

// layer2: out[v][c] = sp2s[v][c] + mean_u sp2nH[u][c] + b2[c]
// 8 edges per main iteration (2 independent LDG.128 in flight per lane).
__global__ void k_agg2(const float* __restrict__ b2, float* __restrict__ out) {
    int w = (blockIdx.x * blockDim.x + threadIdx.x) >> 5;
    int lane = threadIdx.x & 31;
    if (w >= N_NODES) return;
    int beg = g_off[w];
    int d = g_deg[w];
    int end = beg + d;
    const int colb = (lane & 7) * 8;
    const int sub = lane >> 3;  // 0..3

    float acc[8];
#pragma unroll
    for (int j = 0; j < 8; j++) acc[j] = 0.f;

    int e = beg;
    for (; e + 7 < end; e += 8) {
        int s0 = g_csr[e + sub];
        int s1 = g_csr[e + 4 + sub];
        uint4 r0 = *(const uint4*)(g_sp2nH + (size_t)s0 * 64 + colb);
        uint4 r1 = *(const uint4*)(g_sp2nH + (size_t)s1 * 64 + colb);
#pragma unroll
        for (int q = 0; q < 4; q++) {
            uint32_t u0 = (&r0.x)[q];
            uint32_t u1 = (&r1.x)[q];
            float2 f0 = __half22float2(*(__half2*)&u0);
            float2 f1 = __half22float2(*(__half2*)&u1);
            acc[q * 2 + 0] += f0.x + f1.x;
            acc[q * 2 + 1] += f0.y + f1.y;
        }
    }
    for (; e < end; e += 4) {
        int idx = e + sub;
        if (idx < end) {
            int s = g_csr[idx];
            uint4 r = *(const uint4*)(g_sp2nH + (size_t)s * 64 + colb);
#pragma unroll
            for (int q = 0; q < 4; q++) {
                uint32_t u = (&r.x)[q];
                float2 f = __half22float2(*(__half2*)&u);
                acc[q * 2 + 0] += f.x;
                acc[q * 2 + 1] += f.y;
            }
        }
    }
#pragma unroll
    for (int j = 0; j < 8; j++) {
        acc[j] += __shfl_xor_sync(0xFFFFFFFF, acc[j], 8);
        acc[j] += __shfl_xor_sync(0xFFFFFFFF, acc[j], 16);
    }

    if (lane < 8) {
        float inv = (d > 0) ? 1.0f / (float)d : 0.0f;
        uint4 sr = *(const uint4*)(g_sp2s + (size_t)w * 64 + colb);
        float4 bb0 = *(const float4*)(b2 + colb);
        float4 bb1 = *(const float4*)(b2 + colb + 4);
        float bv[8] = {bb0.x, bb0.y, bb0.z, bb0.w, bb1.x, bb1.y, bb1.z, bb1.w};
        float o[8];
#pragma unroll
        for (int q = 0; q < 4; q++) {
            uint32_t u = (&sr.x)[q];
            float2 s2 = __half22float2(*(__half2*)&u);
            o[q * 2 + 0] = s2.x + acc[q * 2 + 0] * inv + bv[q * 2 + 0];
            o[q * 2 + 1] = s2.y + acc[q * 2 + 1] * inv + bv[q * 2 + 1];
        }
        *(float4*)(out + (size_t)w * 64 + colb)     = make_float4(o[0], o[1], o[2], o[3]);
        *(float4*)(out + (size_t)w * 64 + colb + 4) = make_float4(o[4], o[5], o[6], o[7]);
    }
}

// ---------------- GEMM (tcgen05 on sm_103a; naive fallback otherwise) --------
// A is fp16-precision (exact in tf32, single tile). LAYER 1 reads fp32 feat and
// rounds through fp16 inline (bit-identical to a separate cvt pass); LAYER 2
// reads fp16 g_h. B fp32 weights with hi/lo split in registers.
// LAYER 1 (NT=2): [sp1s | sp1nH](fp16) = round16(feat) @ W1cat^T
// LAYER 2 (NT=1): [sp2s | sp2nH](fp16) = g_h @ W2cat^T
#define GEMM1_SMEM (1024 + 5 * 16384)
#define GEMM2_SMEM (1024 + 3 * 16384)

template <int NT, int LAYER>
__global__ __launch_bounds__(256) void k_gemm(const float* __restrict__ A0) {
    extern __shared__ __align__(1024) char smem[];
    const int tid = threadIdx.x;
    const int row0 = blockIdx.x * 128;
    const float* Wb = (LAYER == 1) ? g_W1cat : g_W2cat;

#if HAS_TC
    const uint32_t sb = smem_u32(smem);
    const uint32_t ctrl = sb;
    const uint32_t mb = sb + 16;
    const uint32_t smA = sb + 1024;
    uint32_t smBh[2], smBl[2];
    smBh[0] = smA + 16384;
    smBl[0] = smBh[0] + 16384;
    smBh[1] = smBl[0] + 16384;
    smBl[1] = smBh[1] + 16384;

    const int wid = tid >> 5;
    const int lane = tid & 31;

    if (wid == 0) {
        TC_ALLOC(ctrl, NT * 128);
        TC_RELINQ();
    }
    if (tid == 0) MBAR_INIT(mb, 1);
    __syncthreads();
    uint32_t tmem;
    asm volatile("ld.shared.b32 %0, [%1];" : "=r"(tmem) : "r"(ctrl));

    int ph = 0;
    for (int c = 0; c < 4; c++) {
        if (c > 0) { mbar_wait(mb, ph); ph ^= 1; }
        const int k0 = c * 32;

#pragma unroll
        for (int i = 0; i < 4; i++) {
            int slot = tid * 4 + i;       // 0..1023
            int rw = slot >> 3;           // 0..127
            int c16 = slot & 7;           // 0..7
            uint32_t bo = rw * 128 + c16 * 16;
            uint32_t sw = bo ^ ((bo >> 3) & 0x70);
            int r = row0 + rw;
            // A: fp16-precision values as fp32 (exact in tf32), single tile
            float4 av = make_float4(0.f, 0.f, 0.f, 0.f);
            if (r < N_NODES) {
                if (LAYER == 1) {
                    // inline fp32 -> fp16(rn) -> fp32: bit-identical to cvt+fp16 load
                    float4 fv = *(const float4*)(A0 + (size_t)r * 128 + k0 + c16 * 4);
                    __half2 h0 = __floats2half2_rn(fv.x, fv.y);
                    __half2 h1 = __floats2half2_rn(fv.z, fv.w);
                    float2 f0 = __half22float2(h0);
                    float2 f1 = __half22float2(h1);
                    av = make_float4(f0.x, f0.y, f1.x, f1.y);
                } else {
                    uint2 hv = *(const uint2*)(g_h + (size_t)r * 128 + k0 + c16 * 4);
                    float2 f0 = __half22float2(*(__half2*)&hv.x);
                    float2 f1 = __half22float2(*(__half2*)&hv.y);
                    av = make_float4(f0.x, f0.y, f1.x, f1.y);
                }
            }
            *(float4*)(smem + (smA - sb) + sw) = av;
            // B tiles (fp32 weights, hi/lo split in registers)
#pragma unroll
            for (int nt = 0; nt < NT; nt++) {
                float4 bv = *(const float4*)(Wb + (size_t)(nt * 128 + rw) * 128 + k0 + c16 * 4);
                float4 bh, bl;
                bh.x = tf32r(bv.x); bl.x = tf32r(bv.x - bh.x);
                bh.y = tf32r(bv.y); bl.y = tf32r(bv.y - bh.y);
                bh.z = tf32r(bv.z); bl.z = tf32r(bv.z - bh.z);
                bh.w = tf32r(bv.w); bl.w = tf32r(bv.w - bh.w);
                *(float4*)(smem + (smBh[nt] - sb) + sw) = bh;
                *(float4*)(smem + (smBl[nt] - sb) + sw) = bl;
            }
        }
        FENCE_ASYNC();
        __syncthreads();
        if (wid == 0) {
            if (elect_one()) {
                uint64_t ad = mk_desc(smA);
#pragma unroll
                for (int nt = 0; nt < NT; nt++) {
                    uint64_t bdh = mk_desc(smBh[nt]), bdl = mk_desc(smBl[nt]);
                    uint32_t dt = tmem + nt * 128;
#pragma unroll
                    for (int s = 0; s < 4; s++) {
                        tc_mma_tf32_ss(dt, ad + s * 2, bdh + s * 2, IDESC_TF32, !(c == 0 && s == 0));
                        tc_mma_tf32_ss(dt, ad + s * 2, bdl + s * 2, IDESC_TF32, true);
                    }
                }
                TC_COMMIT(mb);
            }
        }
    }
    mbar_wait(mb, ph);
    TC_FENCE_AFTER();

    // epilogue: warps 0..3 each cover 32 M-rows; paired tcgen05.ld, one wait per 64 cols
    if (wid < 4) {
        int r = row0 + wid * 32 + lane;
        const int NCOL = (LAYER == 1) ? 128 : 64;  // per half
        __half* dst_s = (LAYER == 1) ? g_sp1s : g_sp2s;
        __half* dst_n = (LAYER == 1) ? g_sp1nH : g_sp2nH;
#pragma unroll
        for (int half = 0; half < 2; half++) {
            __half* D = half ? dst_n : dst_s;
            int tb = half * NCOL;
#pragma unroll
            for (int off = 0; off < NCOL; off += 64) {
                uint32_t dr0[32], dr1[32];
                TC_LD_X32(dr0, tmem + tb + off);
                TC_LD_X32(dr1, tmem + tb + off + 32);
                TC_WAIT_LD();
                if (r < N_NODES) {
                    uint32_t pk[32];
#pragma unroll
                    for (int q = 0; q < 16; q++) {
                        __half2 h0 = __floats2half2_rn(__uint_as_float(dr0[2 * q]),
                                                       __uint_as_float(dr0[2 * q + 1]));
                        __half2 h1 = __floats2half2_rn(__uint_as_float(dr1[2 * q]),
                                                       __uint_as_float(dr1[2 * q + 1]));
                        pk[q] = *(uint32_t*)&h0;
                        pk[16 + q] = *(uint32_t*)&h1;
                    }
#pragma unroll
                    for (int q = 0; q < 8; q++)
                        *(uint4*)(D + (size_t)r * NCOL + off + q * 8) =
                            make_uint4(pk[q * 4], pk[q * 4 + 1], pk[q * 4 + 2], pk[q * 4 + 3]);
                }
            }
        }
        TC_FENCE_BEFORE();
    }
    __syncthreads();
    if (wid == 0) TC_DEALLOC(tmem, NT * 128);

#else  // ---------------- naive fallback (non-sm_103a pass; never runs on GB300)
    for (int e = tid; e < 128 * NT * 128; e += 256) {
        int rr = e / (NT * 128);
        int cc = e % (NT * 128);
        int r = row0 + rr;
        if (r >= N_NODES) continue;
        const float* Brow = Wb + (size_t)cc * 128;
        float s = 0.f;
        for (int k = 0; k < 128; k++) {
            float a;
            if (LAYER == 1)
                a = __half2float(__float2half_rn(A0[(size_t)r * 128 + k]));
            else
                a = __half2float(g_h[(size_t)r * 128 + k]);
            s += a * Brow[k];
        }
        if (LAYER == 1) {
            if (cc < 128) g_sp1s[(size_t)r * 128 + cc] = __float2half_rn(s);
            else          g_sp1nH[(size_t)r * 128 + (cc - 128)] = __float2half_rn(s);
        } else {
            if (cc < 64) g_sp2s[(size_t)r * 64 + cc] = __float2half_rn(s);
            else         g_sp2nH[(size_t)r * 64 + (cc - 64)] = __float2half_rn(s);
        }
    }
#endif
}

// ---------------- launch -----------------------------------------------------
extern "C" void kernel_launch(void* const* d_in, const int* in_sizes, int n_in,
                              void* d_out, int out_size) {
    const float* feat = (const float*)d_in[0];
    const int*   esrc = (const int*)d_in[1];
    const int*   edst = (const int*)d_in[2];
    const float* W1s  = (const float*)d_in[3];
    const float* W1n  = (const float*)d_in[4];
    const float* b1   = (const float*)d_in[5];
    const float* W2s  = (const float*)d_in[6];
    const float* W2n  = (const float*)d_in[7];
    const float* b2   = (const float*)d_in[8];
    float* out = (float*)d_out;

    static cudaStream_t s1 = nullptr;
    static cudaEvent_t e0 = nullptr, e1 = nullptr;
    if (!s1) {
        cudaStreamCreateWithFlags(&s1, cudaStreamNonBlocking);
        cudaEventCreateWithFlags(&e0, cudaEventDisableTiming);
        cudaEventCreateWithFlags(&e1, cudaEventDisableTiming);
    }

    cudaFuncSetAttribute(k_gemm<2, 1>, cudaFuncAttributeMaxDynamicSharedMemorySize, GEMM1_SMEM);
    cudaFuncSetAttribute(k_gemm<1, 2>, cudaFuncAttributeMaxDynamicSharedMemorySize, GEMM2_SMEM);

    const int TB = 256;

    // ---- fork: stream s1 does pack + layer-1 projection GEMM (graph-independent)
    cudaEventRecord(e0, 0);
    cudaStreamWaitEvent(s1, e0, 0);
    k_pack<<<(256 * 128 + 128 * 128 + TB - 1) / TB, TB, 0, s1>>>(W1s, W1n, W2s, W2n);
    k_gemm<2, 1><<<TOT_TILES, 256, GEMM1_SMEM, s1>>>(feat);
    cudaEventRecord(e1, s1);

    // ---- default stream: CSR build
    k_zero_deg<<<(N_NODES + TB - 1) / TB, TB>>>();
    k_hist<<<(N_EDGES + TB - 1) / TB, TB>>>(edst);
    k_scan1<<<(N_NODES + 1023) / 1024, 1024>>>();
    k_scan3<<<(N_NODES + TB - 1) / TB, TB>>>();
    k_fill<<<(N_EDGES + TB - 1) / TB, TB>>>(esrc, edst);

    // ---- join
    cudaStreamWaitEvent(0, e1, 0);

    // layer 1 aggregate (+self+bias+relu), layer 2 projection, layer 2 aggregate
    k_agg1<<<(N_NODES * 32 + TB - 1) / TB, TB>>>(b1);
    k_gemm<1, 2><<<TOT_TILES, 256, GEMM2_SMEM>>>(nullptr);
    k_agg2<<<(N_NODES * 32 + TB - 1) / TB, TB>>>(b2, out);
}

// round 16
// speedup vs baseline: 1.1556x; 1.0471x over previous
#include <cuda_runtime.h>
#include <cuda_fp16.h>
#include <cstdint>

#define N_NODES 100000
#define N_EDGES 1600000
// IN_F = HID_F = 128, OUT_F = 64

#if defined(__CUDA_ARCH_FEAT_SM103_ALL)
#define HAS_TC 1
#else
#define HAS_TC 0
#endif

#define TOT_TILES ((N_NODES + 127) / 128)  // 782

// ---------------- scratch (device globals; no allocation allowed) ----------
__device__ int    g_deg[N_NODES];
__device__ int    g_off[N_NODES];
__device__ int    g_cur[N_NODES];
__device__ int    g_csr[N_EDGES];
__device__ int    g_bsum[128];
__device__ __half g_sp1s[(size_t)N_NODES * 128];   // feat @ W1_self (fp16)
__device__ __half g_sp1nH[(size_t)N_NODES * 128];  // feat @ W1_neigh (fp16)
__device__ __half g_h[(size_t)N_NODES * 128];      // relu(layer1) (fp16)
__device__ __half g_sp2s[(size_t)N_NODES * 64];    // h @ W2_self (fp16)
__device__ __half g_sp2nH[(size_t)N_NODES * 64];   // h @ W2_neigh (fp16)
// weights transposed [n][k], 2-term fp16 split (hi + residual; ~22-bit effective)
__device__ __half g_W1h[256 * 128];
__device__ __half g_W1l[256 * 128];
__device__ __half g_W2h[128 * 128];
__device__ __half g_W2l[128 * 128];

// ---------------- generic helpers -------------------------------------------
__device__ __forceinline__ uint32_t smem_u32(const void* p) {
    uint32_t a;
    asm("{ .reg .u64 t; cvta.to.shared.u64 t, %1; cvt.u32.u64 %0, t; }" : "=r"(a) : "l"(p));
    return a;
}

#if HAS_TC
__device__ __forceinline__ uint32_t elect_one() {
    uint32_t p;
    asm volatile("{ .reg .pred p; elect.sync _|p, 0xFFFFFFFF; selp.b32 %0, 1, 0, p; }" : "=r"(p));
    return p;
}
#define MBAR_INIT(addr, cnt) \
    asm volatile("mbarrier.init.shared.b64 [%0], %1;" :: "r"(addr), "r"(cnt) : "memory")
__device__ __forceinline__ void mbar_wait(uint32_t addr, int phase) {
    asm volatile(
        "{\n\t.reg .pred P;\n\t"
        "WL_%=:\n\t"
        "mbarrier.try_wait.parity.acquire.cta.shared::cta.b64 P, [%0], %1, 0x989680;\n\t"
        "@P bra.uni WD_%=;\n\t"
        "bra.uni WL_%=;\n\t"
        "WD_%=:\n\t}"
        :: "r"(addr), "r"(phase) : "memory");
}
#define TC_ALLOC(ctrl, n) \
    asm volatile("tcgen05.alloc.cta_group::1.sync.aligned.shared::cta.b32 [%0], %1;" :: "r"(ctrl), "r"(n) : "memory")
#define TC_RELINQ() \
    asm volatile("tcgen05.relinquish_alloc_permit.cta_group::1.sync.aligned;")
#define TC_DEALLOC(t, n) \
    asm volatile("tcgen05.dealloc.cta_group::1.sync.aligned.b32 %0, %1;" :: "r"(t), "r"(n))
#define TC_COMMIT(mb) \
    asm volatile("tcgen05.commit.cta_group::1.mbarrier::arrive::one.shared::cluster.b64 [%0];" :: "r"(mb) : "memory")
#define TC_FENCE_AFTER()  asm volatile("tcgen05.fence::after_thread_sync;" ::: "memory")
#define TC_FENCE_BEFORE() asm volatile("tcgen05.fence::before_thread_sync;" ::: "memory")
#define TC_WAIT_LD()      asm volatile("tcgen05.wait::ld.sync.aligned;" ::: "memory")
#define FENCE_ASYNC()     asm volatile("fence.proxy.async.shared::cta;" ::: "memory")

// fp16 SS MMA, cta_group::1, fp32 accumulate (verified correct in round 9)
__device__ __forceinline__ void tc_mma_f16_ss(uint32_t d_tmem, uint64_t a_desc,
                                              uint64_t b_desc, uint32_t idesc, bool acc) {
    uint32_t en = acc ? 1u : 0u;
    asm volatile(
        "{\n\t.reg .pred p;\n\t"
        "setp.ne.u32 p, %5, 0;\n\t"
        "tcgen05.mma.cta_group::1.kind::f16 [%0], %1, %2, %3, {%4, %4, %4, %4}, p;\n\t}"
        :: "r"(d_tmem), "l"(a_desc), "l"(b_desc), "r"(idesc), "r"(0u), "r"(en) : "memory");
}

#define TC_LD_X32(r, a) \
    asm volatile( \
        "tcgen05.ld.sync.aligned.32x32b.x32.b32 " \
        "{%0,%1,%2,%3,%4,%5,%6,%7,%8,%9,%10,%11,%12,%13,%14,%15," \
        "%16,%17,%18,%19,%20,%21,%22,%23,%24,%25,%26,%27,%28,%29,%30,%31}, [%32];" \
        : "=r"((r)[0]),"=r"((r)[1]),"=r"((r)[2]),"=r"((r)[3]),"=r"((r)[4]),"=r"((r)[5]),"=r"((r)[6]),"=r"((r)[7]), \
          "=r"((r)[8]),"=r"((r)[9]),"=r"((r)[10]),"=r"((r)[11]),"=r"((r)[12]),"=r"((r)[13]),"=r"((r)[14]),"=r"((r)[15]), \
          "=r"((r)[16]),"=r"((r)[17]),"=r"((r)[18]),"=r"((r)[19]),"=r"((r)[20]),"=r"((r)[21]),"=r"((r)[22]),"=r"((r)[23]), \
          "=r"((r)[24]),"=r"((r)[25]),"=r"((r)[26]),"=r"((r)[27]),"=r"((r)[28]),"=r"((r)[29]),"=r"((r)[30]),"=r"((r)[31]) \
        : "r"(a))

// SW128 K-major descriptor: layout=2, version=1, SBO=64, LBO=1
__device__ __forceinline__ uint64_t mk_desc(uint32_t addr) {
    return ((uint64_t)2 << 61) | ((uint64_t)1 << 46) | ((uint64_t)64 << 32) |
           ((uint64_t)1 << 16) | (((uint64_t)addr >> 4) & 0x3FFF);
}

// idesc kind::f16: dtype=F32(1<<4), atype=FP16(0), btype=FP16(0), N=128, M=128
#define IDESC_F16 ((1u << 4) | (16u << 17) | (8u << 24))
#endif  // HAS_TC

// ---------------- CSR build -------------------------------------------------
__global__ void k_zero_deg() {
    int i = blockIdx.x * blockDim.x + threadIdx.x;
    if (i < N_NODES) g_deg[i] = 0;
}

__global__ void k_hist(const int* __restrict__ dst) {
    int i = blockIdx.x * blockDim.x + threadIdx.x;
    if (i < N_EDGES) atomicAdd(&g_deg[dst[i]], 1);
}

__global__ void k_scan1() {
    __shared__ int s[1024];
    int tid = threadIdx.x;
    int i = blockIdx.x * 1024 + tid;
    int v = (i < N_NODES) ? g_deg[i] : 0;
    s[tid] = v;
    __syncthreads();
#pragma unroll
    for (int off = 1; off < 1024; off <<= 1) {
        int t = (tid >= off) ? s[tid - off] : 0;
        __syncthreads();
        s[tid] += t;
        __syncthreads();
    }
    if (i < N_NODES) g_off[i] = s[tid] - v;
    if (tid == 1023) g_bsum[blockIdx.x] = s[tid];
}

// fused: each block locally scans the 98 block sums, then applies
__global__ void k_scan3() {
    __shared__ int sbm[128];
    int tid = threadIdx.x;
    if (tid < 128) sbm[tid] = (tid < 98) ? g_bsum[tid] : 0;
    __syncthreads();
#pragma unroll
    for (int off = 1; off < 128; off <<= 1) {
        int t = 0;
        if (tid < 128 && tid >= off) t = sbm[tid - off];
        __syncthreads();
        if (tid < 128) sbm[tid] += t;
        __syncthreads();
    }
    int i = blockIdx.x * blockDim.x + tid;
    if (i < N_NODES) {
        int b = i >> 10;
        int add = (b > 0) ? sbm[b - 1] : 0;
        int o = g_off[i] + add;
        g_off[i] = o;
        g_cur[i] = o;
    }
}

__global__ void k_fill(const int* __restrict__ src, const int* __restrict__ dst) {
    int i = blockIdx.x * blockDim.x + threadIdx.x;
    if (i < N_EDGES) {
        int p = atomicAdd(&g_cur[dst[i]], 1);
        g_csr[p] = src[i];
    }
}

// pack weights transposed ([n][k]) as 2-term fp16 split
__global__ void k_pack(const float* __restrict__ W1s, const float* __restrict__ W1n,
                       const float* __restrict__ W2s, const float* __restrict__ W2n) {
    int i = blockIdx.x * blockDim.x + threadIdx.x;
    if (i < 256 * 128) {
        int n = i >> 7, k = i & 127;
        float v = (n < 128) ? W1s[k * 128 + n] : W1n[k * 128 + (n - 128)];
        __half h = __float2half_rn(v);
        g_W1h[i] = h;
        g_W1l[i] = __float2half_rn(v - __half2float(h));
    } else if (i < 256 * 128 + 128 * 128) {
        int j = i - 256 * 128;
        int n = j >> 7, k = j & 127;
        float v = (n < 64) ? W2s[k * 64 + n] : W2n[k * 64 + (n - 64)];
        __half h = __float2half_rn(v);
        g_W2h[j] = h;
        g_W2l[j] = __float2half_rn(v - __half2float(h));
    }
}

// ---------------- aggregation (warp per destination node) -------------------
// layer1: g_h[v] = relu(sp1s[v] + mean_u sp1nH[u] + b1)
// 4 edges per main iteration (2 independent LDG.128 in flight per lane).
__global__ void k_agg1(const float* __restrict__ b1) {
    int w = (blockIdx.x * blockDim.x + threadIdx.x) >> 5;
    int lane = threadIdx.x & 31;
    if (w >= N_NODES) return;
    int beg = g_off[w];
    int d = g_deg[w];
    int end = beg + d;
    const int colb = (lane & 15) * 8;
    const int half_id = lane >> 4;  // 0 or 1

    float acc[8];
#pragma unroll
    for (int j = 0; j < 8; j++) acc[j] = 0.f;

    int e = beg;
    for (; e + 3 < end; e += 4) {
        int s0 = g_csr[e + half_id];
        int s1 = g_csr[e + 2 + half_id];
        uint4 r0 = *(const uint4*)(g_sp1nH + (size_t)s0 * 128 + colb);
        uint4 r1 = *(const uint4*)(g_sp1nH + (size_t)s1 * 128 + colb);
#pragma unroll
        for (int q = 0; q < 4; q++) {
            uint32_t u0 = (&r0.x)[q];
            uint32_t u1 = (&r1.x)[q];
            float2 f0 = __half22float2(*(__half2*)&u0);
            float2 f1 = __half22float2(*(__half2*)&u1);
            acc[q * 2 + 0] += f0.x + f1.x;
            acc[q * 2 + 1] += f0.y + f1.y;
        }
    }
    for (; e + 1 < end; e += 2) {
        int s0 = g_csr[e + half_id];
        uint4 r0 = *(const uint4*)(g_sp1nH + (size_t)s0 * 128 + colb);
#pragma unroll
        for (int q = 0; q < 4; q++) {
            uint32_t u0 = (&r0.x)[q];
            float2 f0 = __half22float2(*(__half2*)&u0);
            acc[q * 2 + 0] += f0.x;
            acc[q * 2 + 1] += f0.y;
        }
    }
    if (e < end && half_id == 0) {  // odd tail
        int s0 = g_csr[e];
        uint4 r0 = *(const uint4*)(g_sp1nH + (size_t)s0 * 128 + colb);
#pragma unroll
        for (int q = 0; q < 4; q++) {
            uint32_t u0 = (&r0.x)[q];
            float2 f0 = __half22float2(*(__half2*)&u0);
            acc[q * 2 + 0] += f0.x;
            acc[q * 2 + 1] += f0.y;
        }
    }
#pragma unroll
    for (int j = 0; j < 8; j++) acc[j] += __shfl_xor_sync(0xFFFFFFFF, acc[j], 16);

    if (lane < 16) {
        float inv = (d > 0) ? 1.0f / (float)d : 0.0f;
        uint4 sr = *(const uint4*)(g_sp1s + (size_t)w * 128 + colb);
        float4 bb0 = *(const float4*)(b1 + colb);
        float4 bb1 = *(const float4*)(b1 + colb + 4);
        float bv[8] = {bb0.x, bb0.y, bb0.z, bb0.w, bb1.x, bb1.y, bb1.z, bb1.w};
        uint32_t outp[4];
#pragma unroll
        for (int q = 0; q < 4; q++) {
            uint32_t u = (&sr.x)[q];
            float2 s2 = __half22float2(*(__half2*)&u);
            float o0 = fmaxf(s2.x + acc[q * 2 + 0] * inv + bv[q * 2 + 0], 0.f);
            float o1 = fmaxf(s2.y + acc[q * 2 + 1] * inv + bv[q * 2 + 1], 0.f);
            __half2 hh = __floats2half2_rn(o0, o1);
            outp[q] = *(uint32_t*)&hh;
        }
        *(uint4*)(g_h + (size_t)w * 128 + colb) = make_uint4(outp[0], outp[1], outp[2], outp[3]);
    }
}

// layer2: out[v][c] = sp2s[v][c] + mean_u sp2nH[u][c] + b2[c]
// 8 edges per main iteration (2 independent LDG.128 in flight per lane).
__global__ void k_agg2(const float* __restrict__ b2, float* __restrict__ out) {
    int w = (blockIdx.x * blockDim.x + threadIdx.x) >> 5;
    int lane = threadIdx.x & 31;
    if (w >= N_NODES) return;
    int beg = g_off[w];
    int d = g_deg[w];
    int end = beg + d;
    const int colb = (lane & 7) * 8;
    const int sub = lane >> 3;  // 0..3

    float acc[8];
#pragma unroll
    for (int j = 0; j < 8; j++) acc[j] = 0.f;

    int e = beg;
    for (; e + 7 < end; e += 8) {
        int s0 = g_csr[e + sub];
        int s1 = g_csr[e + 4 + sub];
        uint4 r0 = *(const uint4*)(g_sp2nH + (size_t)s0 * 64 + colb);
        uint4 r1 = *(const uint4*)(g_sp2nH + (size_t)s1 * 64 + colb);
#pragma unroll
        for (int q = 0; q < 4; q++) {
            uint32_t u0 = (&r0.x)[q];
            uint32_t u1 = (&r1.x)[q];
            float2 f0 = __half22float2(*(__half2*)&u0);
            float2 f1 = __half22float2(*(__half2*)&u1);
            acc[q * 2 + 0] += f0.x + f1.x;
            acc[q * 2 + 1] += f0.y + f1.y;
        }
    }
    for (; e < end; e += 4) {
        int idx = e + sub;
        if (idx < end) {
            int s = g_csr[idx];
            uint4 r = *(const uint4*)(g_sp2nH + (size_t)s * 64 + colb);
#pragma unroll
            for (int q = 0; q < 4; q++) {
                uint32_t u = (&r.x)[q];
                float2 f = __half22float2(*(__half2*)&u);
                acc[q * 2 + 0] += f.x;
                acc[q * 2 + 1] += f.y;
            }
        }
    }
#pragma unroll
    for (int j = 0; j < 8; j++) {
        acc[j] += __shfl_xor_sync(0xFFFFFFFF, acc[j], 8);
        acc[j] += __shfl_xor_sync(0xFFFFFFFF, acc[j], 16);
    }

    if (lane < 8) {
        float inv = (d > 0) ? 1.0f / (float)d : 0.0f;
        uint4 sr = *(const uint4*)(g_sp2s + (size_t)w * 64 + colb);
        float4 bb0 = *(const float4*)(b2 + colb);
        float4 bb1 = *(const float4*)(b2 + colb + 4);
        float bv[8] = {bb0.x, bb0.y, bb0.z, bb0.w, bb1.x, bb1.y, bb1.z, bb1.w};
        float o[8];
#pragma unroll
        for (int q = 0; q < 4; q++) {
            uint32_t u = (&sr.x)[q];
            float2 s2 = __half22float2(*(__half2*)&u);
            o[q * 2 + 0] = s2.x + acc[q * 2 + 0] * inv + bv[q * 2 + 0];
            o[q * 2 + 1] = s2.y + acc[q * 2 + 1] * inv + bv[q * 2 + 1];
        }
        *(float4*)(out + (size_t)w * 64 + colb)     = make_float4(o[0], o[1], o[2], o[3]);
        *(float4*)(out + (size_t)w * 64 + colb + 4) = make_float4(o[4], o[5], o[6], o[7]);
    }
}

// ---------------- GEMM (tcgen05 kind::f16, 2-chunk pipelined) ----------------
// A fp16 tiles (LAYER 1: inline fp32->fp16 cvt from feat, bit-identical to cvt
// kernel; LAYER 2: straight copies from g_h). B = Wh+Wl fp16 2-term split
// (residual ~2^-21 -> effectively exact). fp32 accumulate in TMEM.
// Tiles: 128 rows x 64 fp16 (16KB, SW128 K-major). 2 chunks cover K=128.
// LAYER 1 (NT=2): [sp1s | sp1nH] = round16(feat) @ W1^T
// LAYER 2 (NT=1): [sp2s | sp2nH] = g_h @ W2^T
#define GEMM1_SMEM (1024 + 16384 + 4 * 16384)  // 83968
#define GEMM2_SMEM (1024 + 16384 + 2 * 16384)  // 50176

template <int NT, int LAYER>
__global__ __launch_bounds__(256) void k_gemm(const float* __restrict__ A0) {
    extern __shared__ __align__(1024) char smem[];
    const int tid = threadIdx.x;
    const int row0 = blockIdx.x * 128;
    const __half* Wh = (LAYER == 1) ? g_W1h : g_W2h;
    const __half* Wl = (LAYER == 1) ? g_W1l : g_W2l;

#if HAS_TC
    const uint32_t sb = smem_u32(smem);
    const uint32_t ctrl = sb;
    const uint32_t mb = sb + 16;
    const uint32_t smA = sb + 1024;
    uint32_t smBh[2], smBl[2];
    smBh[0] = smA + 16384;
    smBl[0] = smBh[0] + 16384;
    smBh[1] = smBl[0] + 16384;
    smBl[1] = smBh[1] + 16384;

    const int wid = tid >> 5;
    const int lane = tid & 31;

    if (wid == 0) {
        TC_ALLOC(ctrl, NT * 128);
        TC_RELINQ();
    }
    if (tid == 0) MBAR_INIT(mb, 1);
    __syncthreads();
    uint32_t tmem;
    asm volatile("ld.shared.b32 %0, [%1];" : "=r"(tmem) : "r"(ctrl));

    int ph = 0;
    for (int c = 0; c < 2; c++) {
        if (c > 0) { mbar_wait(mb, ph); ph ^= 1; }
        const int k0 = c * 64;

#pragma unroll
        for (int i = 0; i < 4; i++) {
            int slot = tid * 4 + i;       // 0..1023 (16B granules of a 128x64 fp16 tile)
            int rw = slot >> 3;           // 0..127
            int c8 = slot & 7;            // 0..7 (8 fp16 per granule)
            uint32_t bo = rw * 128 + c8 * 16;
            uint32_t sw = bo ^ ((bo >> 3) & 0x70);
            int r = row0 + rw;
            // A: fp16 granule
            uint4 av = make_uint4(0, 0, 0, 0);
            if (r < N_NODES) {
                if (LAYER == 1) {
                    // inline fp32 -> fp16(rn): bit-identical to a cvt pass
                    const float4* p = (const float4*)(A0 + (size_t)r * 128 + k0 + c8 * 8);
                    float4 a = p[0], b = p[1];
                    __half2 h0 = __floats2half2_rn(a.x, a.y);
                    __half2 h1 = __floats2half2_rn(a.z, a.w);
                    __half2 h2 = __floats2half2_rn(b.x, b.y);
                    __half2 h3 = __floats2half2_rn(b.z, b.w);
                    av = make_uint4(*(uint32_t*)&h0, *(uint32_t*)&h1,
                                    *(uint32_t*)&h2, *(uint32_t*)&h3);
                } else {
                    av = *(const uint4*)(g_h + (size_t)r * 128 + k0 + c8 * 8);
                }
            }
            *(uint4*)(smem + (smA - sb) + sw) = av;
            // B tiles: straight 16B copies of fp16 hi and lo
#pragma unroll
            for (int nt = 0; nt < NT; nt++) {
                size_t src = (size_t)(nt * 128 + rw) * 128 + k0 + c8 * 8;
                *(uint4*)(smem + (smBh[nt] - sb) + sw) = *(const uint4*)(Wh + src);
                *(uint4*)(smem + (smBl[nt] - sb) + sw) = *(const uint4*)(Wl + src);
            }
        }
        FENCE_ASYNC();
        __syncthreads();
        if (wid == 0) {
            if (elect_one()) {
                uint64_t ad = mk_desc(smA);
#pragma unroll
                for (int nt = 0; nt < NT; nt++) {
                    uint64_t bdh = mk_desc(smBh[nt]), bdl = mk_desc(smBl[nt]);
                    uint32_t dt = tmem + nt * 128;
#pragma unroll
                    for (int s = 0; s < 4; s++) {  // K=16 per f16 MMA, 4 steps = K64
                        tc_mma_f16_ss(dt, ad + s * 2, bdh + s * 2, IDESC_F16, !(c == 0 && s == 0));
                        tc_mma_f16_ss(dt, ad + s * 2, bdl + s * 2, IDESC_F16, true);
                    }
                }
                TC_COMMIT(mb);
            }
        }
    }
    mbar_wait(mb, ph);
    TC_FENCE_AFTER();

    // epilogue: warps 0..3 each cover 32 M-rows; paired tcgen05.ld, one wait per 64 cols
    if (wid < 4) {
        int r = row0 + wid * 32 + lane;
        const int NCOL = (LAYER == 1) ? 128 : 64;  // per half
        __half* dst_s = (LAYER == 1) ? g_sp1s : g_sp2s;
        __half* dst_n = (LAYER == 1) ? g_sp1nH : g_sp2nH;
#pragma unroll
        for (int half = 0; half < 2; half++) {
            __half* D = half ? dst_n : dst_s;
            int tb = half * NCOL;
#pragma unroll
            for (int off = 0; off < NCOL; off += 64) {
                uint32_t dr0[32], dr1[32];
                TC_LD_X32(dr0, tmem + tb + off);
                TC_LD_X32(dr1, tmem + tb + off + 32);
                TC_WAIT_LD();
                if (r < N_NODES) {
                    uint32_t pk[32];
#pragma unroll
                    for (int q = 0; q < 16; q++) {
                        __half2 h0 = __floats2half2_rn(__uint_as_float(dr0[2 * q]),
                                                       __uint_as_float(dr0[2 * q + 1]));
                        __half2 h1 = __floats2half2_rn(__uint_as_float(dr1[2 * q]),
                                                       __uint_as_float(dr1[2 * q + 1]));
                        pk[q] = *(uint32_t*)&h0;
                        pk[16 + q] = *(uint32_t*)&h1;
                    }
#pragma unroll
                    for (int q = 0; q < 8; q++)
                        *(uint4*)(D + (size_t)r * NCOL + off + q * 8) =
                            make_uint4(pk[q * 4], pk[q * 4 + 1], pk[q * 4 + 2], pk[q * 4 + 3]);
                }
            }
        }
        TC_FENCE_BEFORE();
    }
    __syncthreads();
    if (wid == 0) TC_DEALLOC(tmem, NT * 128);

#else  // ---------------- naive fallback (non-sm_103a pass; never runs on GB300)
    for (int e = tid; e < 128 * NT * 128; e += 256) {
        int rr = e / (NT * 128);
        int cc = e % (NT * 128);
        int r = row0 + rr;
        if (r >= N_NODES) continue;
        float s = 0.f;
        for (int k = 0; k < 128; k++) {
            float a;
            if (LAYER == 1)
                a = __half2float(__float2half_rn(A0[(size_t)r * 128 + k]));
            else
                a = __half2float(g_h[(size_t)r * 128 + k]);
            float b = __half2float(Wh[(size_t)cc * 128 + k]) + __half2float(Wl[(size_t)cc * 128 + k]);
            s += a * b;
        }
        if (LAYER == 1) {
            if (cc < 128) g_sp1s[(size_t)r * 128 + cc] = __float2half_rn(s);
            else          g_sp1nH[(size_t)r * 128 + (cc - 128)] = __float2half_rn(s);
        } else {
            if (cc < 64) g_sp2s[(size_t)r * 64 + cc] = __float2half_rn(s);
            else         g_sp2nH[(size_t)r * 64 + (cc - 64)] = __float2half_rn(s);
        }
    }
#endif
}

// ---------------- launch -----------------------------------------------------
extern "C" void kernel_launch(void* const* d_in, const int* in_sizes, int n_in,
                              void* d_out, int out_size) {
    const float* feat = (const float*)d_in[0];
    const int*   esrc = (const int*)d_in[1];
    const int*   edst = (const int*)d_in[2];
    const float* W1s  = (const float*)d_in[3];
    const float* W1n  = (const float*)d_in[4];
    const float* b1   = (const float*)d_in[5];
    const float* W2s  = (const float*)d_in[6];
    const float* W2n  = (const float*)d_in[7];
    const float* b2   = (const float*)d_in[8];
    float* out = (float*)d_out;

    static cudaStream_t s1 = nullptr;
    static cudaEvent_t e0 = nullptr, e1 = nullptr;
    if (!s1) {
        cudaStreamCreateWithFlags(&s1, cudaStreamNonBlocking);
        cudaEventCreateWithFlags(&e0, cudaEventDisableTiming);
        cudaEventCreateWithFlags(&e1, cudaEventDisableTiming);
    }

    cudaFuncSetAttribute(k_gemm<2, 1>, cudaFuncAttributeMaxDynamicSharedMemorySize, GEMM1_SMEM);
    cudaFuncSetAttribute(k_gemm<1, 2>, cudaFuncAttributeMaxDynamicSharedMemorySize, GEMM2_SMEM);

    const int TB = 256;

    // ---- fork: stream s1 does pack + layer-1 projection GEMM (graph-independent)
    cudaEventRecord(e0, 0);
    cudaStreamWaitEvent(s1, e0, 0);
    k_pack<<<(256 * 128 + 128 * 128 + TB - 1) / TB, TB, 0, s1>>>(W1s, W1n, W2s, W2n);
    k_gemm<2, 1><<<TOT_TILES, 256, GEMM1_SMEM, s1>>>(feat);
    cudaEventRecord(e1, s1);

    // ---- default stream: CSR build
    k_zero_deg<<<(N_NODES + TB - 1) / TB, TB>>>();
    k_hist<<<(N_EDGES + TB - 1) / TB, TB>>>(edst);
    k_scan1<<<(N_NODES + 1023) / 1024, 1024>>>();
    k_scan3<<<(N_NODES + TB - 1) / TB, TB>>>();
    k_fill<<<(N_EDGES + TB - 1) / TB, TB>>>(esrc, edst);

    // ---- join
    cudaStreamWaitEvent(0, e1, 0);

    // layer 1 aggregate (+self+bias+relu), layer 2 projection, layer 2 aggregate
    k_agg1<<<(N_NODES * 32 + TB - 1) / TB, TB>>>(b1);
    k_gemm<1, 2><<<TOT_TILES, 256, GEMM2_SMEM>>>(nullptr);
    k_agg2<<<(N_NODES * 32 + TB - 1) / TB, TB>>>(b2, out);
}

// round 17
// speedup vs baseline: 1.1993x; 1.0378x over previous
#include <cuda_runtime.h>
#include <cuda_fp16.h>
#include <cstdint>

#define N_NODES 100000
#define N_EDGES 1600000
// IN_F = HID_F = 128, OUT_F = 64

#if defined(__CUDA_ARCH_FEAT_SM103_ALL)
#define HAS_TC 1
#else
#define HAS_TC 0
#endif

#define TOT_TILES ((N_NODES + 127) / 128)  // 782

// ---------------- scratch (device globals; no allocation allowed) ----------
__device__ int    g_deg[N_NODES];
__device__ int    g_off[N_NODES];
__device__ int    g_cur[N_NODES];
__device__ int    g_csr[N_EDGES];
__device__ int    g_bsum[128];
__device__ __half g_sp1s[(size_t)N_NODES * 128];   // feat @ W1_self (fp16)
__device__ __half g_sp1nH[(size_t)N_NODES * 128];  // feat @ W1_neigh (fp16)
__device__ __half g_h[(size_t)N_NODES * 128];      // relu(layer1) (fp16)
__device__ __half g_sp2s[(size_t)N_NODES * 64];    // h @ W2_self (fp16)
__device__ __half g_sp2nH[(size_t)N_NODES * 64];   // h @ W2_neigh (fp16)
// weights transposed [n][k], 2-term fp16 split (hi + residual)
__device__ __half g_W1h[256 * 128];
__device__ __half g_W1l[256 * 128];
__device__ __half g_W2h[128 * 128];

// ---------------- generic helpers -------------------------------------------
__device__ __forceinline__ uint32_t smem_u32(const void* p) {
    uint32_t a;
    asm("{ .reg .u64 t; cvta.to.shared.u64 t, %1; cvt.u32.u64 %0, t; }" : "=r"(a) : "l"(p));
    return a;
}

#if HAS_TC
__device__ __forceinline__ uint32_t elect_one() {
    uint32_t p;
    asm volatile("{ .reg .pred p; elect.sync _|p, 0xFFFFFFFF; selp.b32 %0, 1, 0, p; }" : "=r"(p));
    return p;
}
#define MBAR_INIT(addr, cnt) \
    asm volatile("mbarrier.init.shared.b64 [%0], %1;" :: "r"(addr), "r"(cnt) : "memory")
__device__ __forceinline__ void mbar_wait(uint32_t addr, int phase) {
    asm volatile(
        "{\n\t.reg .pred P;\n\t"
        "WL_%=:\n\t"
        "mbarrier.try_wait.parity.acquire.cta.shared::cta.b64 P, [%0], %1, 0x989680;\n\t"
        "@P bra.uni WD_%=;\n\t"
        "bra.uni WL_%=;\n\t"
        "WD_%=:\n\t}"
        :: "r"(addr), "r"(phase) : "memory");
}
#define TC_ALLOC(ctrl, n) \
    asm volatile("tcgen05.alloc.cta_group::1.sync.aligned.shared::cta.b32 [%0], %1;" :: "r"(ctrl), "r"(n) : "memory")
#define TC_RELINQ() \
    asm volatile("tcgen05.relinquish_alloc_permit.cta_group::1.sync.aligned;")
#define TC_DEALLOC(t, n) \
    asm volatile("tcgen05.dealloc.cta_group::1.sync.aligned.b32 %0, %1;" :: "r"(t), "r"(n))
#define TC_COMMIT(mb) \
    asm volatile("tcgen05.commit.cta_group::1.mbarrier::arrive::one.shared::cluster.b64 [%0];" :: "r"(mb) : "memory")
#define TC_FENCE_AFTER()  asm volatile("tcgen05.fence::after_thread_sync;" ::: "memory")
#define TC_FENCE_BEFORE() asm volatile("tcgen05.fence::before_thread_sync;" ::: "memory")
#define TC_WAIT_LD()      asm volatile("tcgen05.wait::ld.sync.aligned;" ::: "memory")
#define FENCE_ASYNC()     asm volatile("fence.proxy.async.shared::cta;" ::: "memory")

// fp16 SS MMA, cta_group::1, fp32 accumulate
__device__ __forceinline__ void tc_mma_f16_ss(uint32_t d_tmem, uint64_t a_desc,
                                              uint64_t b_desc, uint32_t idesc, bool acc) {
    uint32_t en = acc ? 1u : 0u;
    asm volatile(
        "{\n\t.reg .pred p;\n\t"
        "setp.ne.u32 p, %5, 0;\n\t"
        "tcgen05.mma.cta_group::1.kind::f16 [%0], %1, %2, %3, {%4, %4, %4, %4}, p;\n\t}"
        :: "r"(d_tmem), "l"(a_desc), "l"(b_desc), "r"(idesc), "r"(0u), "r"(en) : "memory");
}

#define TC_LD_X32(r, a) \
    asm volatile( \
        "tcgen05.ld.sync.aligned.32x32b.x32.b32 " \
        "{%0,%1,%2,%3,%4,%5,%6,%7,%8,%9,%10,%11,%12,%13,%14,%15," \
        "%16,%17,%18,%19,%20,%21,%22,%23,%24,%25,%26,%27,%28,%29,%30,%31}, [%32];" \
        : "=r"((r)[0]),"=r"((r)[1]),"=r"((r)[2]),"=r"((r)[3]),"=r"((r)[4]),"=r"((r)[5]),"=r"((r)[6]),"=r"((r)[7]), \
          "=r"((r)[8]),"=r"((r)[9]),"=r"((r)[10]),"=r"((r)[11]),"=r"((r)[12]),"=r"((r)[13]),"=r"((r)[14]),"=r"((r)[15]), \
          "=r"((r)[16]),"=r"((r)[17]),"=r"((r)[18]),"=r"((r)[19]),"=r"((r)[20]),"=r"((r)[21]),"=r"((r)[22]),"=r"((r)[23]), \
          "=r"((r)[24]),"=r"((r)[25]),"=r"((r)[26]),"=r"((r)[27]),"=r"((r)[28]),"=r"((r)[29]),"=r"((r)[30]),"=r"((r)[31]) \
        : "r"(a))

// SW128 K-major descriptor: layout=2, version=1, SBO=64, LBO=1
__device__ __forceinline__ uint64_t mk_desc(uint32_t addr) {
    return ((uint64_t)2 << 61) | ((uint64_t)1 << 46) | ((uint64_t)64 << 32) |
           ((uint64_t)1 << 16) | (((uint64_t)addr >> 4) & 0x3FFF);
}

// idesc kind::f16: dtype=F32(1<<4), atype=FP16(0), btype=FP16(0), N=128, M=128
#define IDESC_F16 ((1u << 4) | (16u << 17) | (8u << 24))
#endif  // HAS_TC

// ---------------- CSR build -------------------------------------------------
__global__ void k_zero_deg() {
    int i = blockIdx.x * blockDim.x + threadIdx.x;
    if (i < N_NODES) g_deg[i] = 0;
}

__global__ void k_hist(const int* __restrict__ dst) {
    int i = blockIdx.x * blockDim.x + threadIdx.x;
    if (i < N_EDGES) atomicAdd(&g_deg[dst[i]], 1);
}

__global__ void k_scan1() {
    __shared__ int s[1024];
    int tid = threadIdx.x;
    int i = blockIdx.x * 1024 + tid;
    int v = (i < N_NODES) ? g_deg[i] : 0;
    s[tid] = v;
    __syncthreads();
#pragma unroll
    for (int off = 1; off < 1024; off <<= 1) {
        int t = (tid >= off) ? s[tid - off] : 0;
        __syncthreads();
        s[tid] += t;
        __syncthreads();
    }
    if (i < N_NODES) g_off[i] = s[tid] - v;
    if (tid == 1023) g_bsum[blockIdx.x] = s[tid];
}

// fused: each block locally scans the 98 block sums, then applies
__global__ void k_scan3() {
    __shared__ int sbm[128];
    int tid = threadIdx.x;
    if (tid < 128) sbm[tid] = (tid < 98) ? g_bsum[tid] : 0;
    __syncthreads();
#pragma unroll
    for (int off = 1; off < 128; off <<= 1) {
        int t = 0;
        if (tid < 128 && tid >= off) t = sbm[tid - off];
        __syncthreads();
        if (tid < 128) sbm[tid] += t;
        __syncthreads();
    }
    int i = blockIdx.x * blockDim.x + tid;
    if (i < N_NODES) {
        int b = i >> 10;
        int add = (b > 0) ? sbm[b - 1] : 0;
        int o = g_off[i] + add;
        g_off[i] = o;
        g_cur[i] = o;
    }
}

__global__ void k_fill(const int* __restrict__ src, const int* __restrict__ dst) {
    int i = blockIdx.x * blockDim.x + threadIdx.x;
    if (i < N_EDGES) {
        int p = atomicAdd(&g_cur[dst[i]], 1);
        g_csr[p] = src[i];
    }
}

// pack weights transposed ([n][k]); W1 as 2-term fp16 split, W2 hi-only
__global__ void k_pack(const float* __restrict__ W1s, const float* __restrict__ W1n,
                       const float* __restrict__ W2s, const float* __restrict__ W2n) {
    int i = blockIdx.x * blockDim.x + threadIdx.x;
    if (i < 256 * 128) {
        int n = i >> 7, k = i & 127;
        float v = (n < 128) ? W1s[k * 128 + n] : W1n[k * 128 + (n - 128)];
        __half h = __float2half_rn(v);
        g_W1h[i] = h;
        g_W1l[i] = __float2half_rn(v - __half2float(h));
    } else if (i < 256 * 128 + 128 * 128) {
        int j = i - 256 * 128;
        int n = j >> 7, k = j & 127;
        float v = (n < 64) ? W2s[k * 64 + n] : W2n[k * 64 + (n - 64)];
        g_W2h[j] = __float2half_rn(v);
    }
}

// ---------------- aggregation (warp per destination node) -------------------
// layer1: g_h[v] = relu(sp1s[v] + mean_u sp1nH[u] + b1)
// 4 edges per main iteration (2 independent LDG.128 in flight per lane).
__global__ void k_agg1(const float* __restrict__ b1) {
    int w = (blockIdx.x * blockDim.x + threadIdx.x) >> 5;
    int lane = threadIdx.x & 31;
    if (w >= N_NODES) return;
    int beg = g_off[w];
    int d = g_deg[w];
    int end = beg + d;
    const int colb = (lane & 15) * 8;
    const int half_id = lane >> 4;  // 0 or 1

    float acc[8];
#pragma unroll
    for (int j = 0; j < 8; j++) acc[j] = 0.f;

    int e = beg;
    for (; e + 3 < end; e += 4) {
        int s0 = g_csr[e + half_id];
        int s1 = g_csr[e + 2 + half_id];
        uint4 r0 = *(const uint4*)(g_sp1nH + (size_t)s0 * 128 + colb);
        uint4 r1 = *(const uint4*)(g_sp1nH + (size_t)s1 * 128 + colb);
#pragma unroll
        for (int q = 0; q < 4; q++) {
            uint32_t u0 = (&r0.x)[q];
            uint32_t u1 = (&r1.x)[q];
            float2 f0 = __half22float2(*(__half2*)&u0);
            float2 f1 = __half22float2(*(__half2*)&u1);
            acc[q * 2 + 0] += f0.x + f1.x;
            acc[q * 2 + 1] += f0.y + f1.y;
        }
    }
    for (; e + 1 < end; e += 2) {
        int s0 = g_csr[e + half_id];
        uint4 r0 = *(const uint4*)(g_sp1nH + (size_t)s0 * 128 + colb);
#pragma unroll
        for (int q = 0; q < 4; q++) {
            uint32_t u0 = (&r0.x)[q];
            float2 f0 = __half22float2(*(__half2*)&u0);
            acc[q * 2 + 0] += f0.x;
            acc[q * 2 + 1] += f0.y;
        }
    }
    if (e < end && half_id == 0) {  // odd tail
        int s0 = g_csr[e];
        uint4 r0 = *(const uint4*)(g_sp1nH + (size_t)s0 * 128 + colb);
#pragma unroll
        for (int q = 0; q < 4; q++) {
            uint32_t u0 = (&r0.x)[q];
            float2 f0 = __half22float2(*(__half2*)&u0);
            acc[q * 2 + 0] += f0.x;
            acc[q * 2 + 1] += f0.y;
        }
    }
#pragma unroll
    for (int j = 0; j < 8; j++) acc[j] += __shfl_xor_sync(0xFFFFFFFF, acc[j], 16);

    if (lane < 16) {
        float inv = (d > 0) ? 1.0f / (float)d : 0.0f;
        uint4 sr = *(const uint4*)(g_sp1s + (size_t)w * 128 + colb);
        float4 bb0 = *(const float4*)(b1 + colb);
        float4 bb1 = *(const float4*)(b1 + colb + 4);
        float bv[8] = {bb0.x, bb0.y, bb0.z, bb0.w, bb1.x, bb1.y, bb1.z, bb1.w};
        uint32_t outp[4];
#pragma unroll
        for (int q = 0; q < 4; q++) {
            uint32_t u = (&sr.x)[q];
            float2 s2 = __half22float2(*(__half2*)&u);
            float o0 = fmaxf(s2.x + acc[q * 2 + 0] * inv + bv[q * 2 + 0], 0.f);
            float o1 = fmaxf(s2.y + acc[q * 2 + 1] * inv + bv[q * 2 + 1], 0.f);
            __half2 hh = __floats2half2_rn(o0, o1);
            outp[q] = *(uint32_t*)&hh;
        }
        *(uint4*)(g_h + (size_t)w * 128 + colb) = make_uint4(outp[0], outp[1], outp[2], outp[3]);
    }
}

// layer2: out[v][c] = sp2s[v][c] + mean_u sp2nH[u][c] + b2[c]
// 8 edges per main iteration (2 independent LDG.128 in flight per lane).
__global__ void k_agg2(const float* __restrict__ b2, float* __restrict__ out) {
    int w = (blockIdx.x * blockDim.x + threadIdx.x) >> 5;
    int lane = threadIdx.x & 31;
    if (w >= N_NODES) return;
    int beg = g_off[w];
    int d = g_deg[w];
    int end = beg + d;
    const int colb = (lane & 7) * 8;
    const int sub = lane >> 3;  // 0..3

    float acc[8];
#pragma unroll
    for (int j = 0; j < 8; j++) acc[j] = 0.f;

    int e = beg;
    for (; e + 7 < end; e += 8) {
        int s0 = g_csr[e + sub];
        int s1 = g_csr[e + 4 + sub];
        uint4 r0 = *(const uint4*)(g_sp2nH + (size_t)s0 * 64 + colb);
        uint4 r1 = *(const uint4*)(g_sp2nH + (size_t)s1 * 64 + colb);
#pragma unroll
        for (int q = 0; q < 4; q++) {
            uint32_t u0 = (&r0.x)[q];
            uint32_t u1 = (&r1.x)[q];
            float2 f0 = __half22float2(*(__half2*)&u0);
            float2 f1 = __half22float2(*(__half2*)&u1);
            acc[q * 2 + 0] += f0.x + f1.x;
            acc[q * 2 + 1] += f0.y + f1.y;
        }
    }
    for (; e < end; e += 4) {
        int idx = e + sub;
        if (idx < end) {
            int s = g_csr[idx];
            uint4 r = *(const uint4*)(g_sp2nH + (size_t)s * 64 + colb);
#pragma unroll
            for (int q = 0; q < 4; q++) {
                uint32_t u = (&r.x)[q];
                float2 f = __half22float2(*(__half2*)&u);
                acc[q * 2 + 0] += f.x;
                acc[q * 2 + 1] += f.y;
            }
        }
    }
#pragma unroll
    for (int j = 0; j < 8; j++) {
        acc[j] += __shfl_xor_sync(0xFFFFFFFF, acc[j], 8);
        acc[j] += __shfl_xor_sync(0xFFFFFFFF, acc[j], 16);
    }

    if (lane < 8) {
        float inv = (d > 0) ? 1.0f / (float)d : 0.0f;
        uint4 sr = *(const uint4*)(g_sp2s + (size_t)w * 64 + colb);
        float4 bb0 = *(const float4*)(b2 + colb);
        float4 bb1 = *(const float4*)(b2 + colb + 4);
        float bv[8] = {bb0.x, bb0.y, bb0.z, bb0.w, bb1.x, bb1.y, bb1.z, bb1.w};
        float o[8];
#pragma unroll
        for (int q = 0; q < 4; q++) {
            uint32_t u = (&sr.x)[q];
            float2 s2 = __half22float2(*(__half2*)&u);
            o[q * 2 + 0] = s2.x + acc[q * 2 + 0] * inv + bv[q * 2 + 0];
            o[q * 2 + 1] = s2.y + acc[q * 2 + 1] * inv + bv[q * 2 + 1];
        }
        *(float4*)(out + (size_t)w * 64 + colb)     = make_float4(o[0], o[1], o[2], o[3]);
        *(float4*)(out + (size_t)w * 64 + colb + 4) = make_float4(o[4], o[5], o[6], o[7]);
    }
}

// ---------------- GEMM (tcgen05 kind::f16, 2-chunk pipelined) ----------------
// A fp16 tiles (LAYER 1: inline fp32->fp16 cvt from feat; LAYER 2: copies from
// g_h). B: LAYER 1 uses Wh+Wl 2-term split (effectively exact); LAYER 2 uses
// hi-only fp16 (final layer, error ~2.4e-4 direct, within budget).
// Tiles: 128 rows x 64 fp16 (16KB, SW128 K-major). 2 chunks cover K=128.
#define GEMM1_SMEM (1024 + 16384 + 4 * 16384)  // 83968
#define GEMM2_SMEM (1024 + 16384 + 1 * 16384)  // 33792

template <int NT, int LAYER, int NBT>
__global__ __launch_bounds__(256) void k_gemm(const float* __restrict__ A0) {
    extern __shared__ __align__(1024) char smem[];
    const int tid = threadIdx.x;
    const int row0 = blockIdx.x * 128;
    const __half* Wh = (LAYER == 1) ? g_W1h : g_W2h;
    const __half* Wl = g_W1l;  // only used when NBT == 2 (layer 1)

#if HAS_TC
    const uint32_t sb = smem_u32(smem);
    const uint32_t ctrl = sb;
    const uint32_t mb = sb + 16;
    const uint32_t smA = sb + 1024;
    uint32_t smBh[2], smBl[2];
    if (NBT == 2) {
        smBh[0] = smA + 16384;
        smBl[0] = smBh[0] + 16384;
        smBh[1] = smBl[0] + 16384;
        smBl[1] = smBh[1] + 16384;
    } else {
        smBh[0] = smA + 16384;
        smBh[1] = smBh[0] + 16384;  // unused for NT=1
        smBl[0] = smBl[1] = 0;
    }

    const int wid = tid >> 5;
    const int lane = tid & 31;

    if (wid == 0) {
        TC_ALLOC(ctrl, NT * 128);
        TC_RELINQ();
    }
    if (tid == 0) MBAR_INIT(mb, 1);
    __syncthreads();
    uint32_t tmem;
    asm volatile("ld.shared.b32 %0, [%1];" : "=r"(tmem) : "r"(ctrl));

    int ph = 0;
    for (int c = 0; c < 2; c++) {
        if (c > 0) { mbar_wait(mb, ph); ph ^= 1; }
        const int k0 = c * 64;

#pragma unroll
        for (int i = 0; i < 4; i++) {
            int slot = tid * 4 + i;       // 0..1023 (16B granules of a 128x64 fp16 tile)
            int rw = slot >> 3;           // 0..127
            int c8 = slot & 7;            // 0..7 (8 fp16 per granule)
            uint32_t bo = rw * 128 + c8 * 16;
            uint32_t sw = bo ^ ((bo >> 3) & 0x70);
            int r = row0 + rw;
            // A: fp16 granule
            uint4 av = make_uint4(0, 0, 0, 0);
            if (r < N_NODES) {
                if (LAYER == 1) {
                    const float4* p = (const float4*)(A0 + (size_t)r * 128 + k0 + c8 * 8);
                    float4 a = p[0], b = p[1];
                    __half2 h0 = __floats2half2_rn(a.x, a.y);
                    __half2 h1 = __floats2half2_rn(a.z, a.w);
                    __half2 h2 = __floats2half2_rn(b.x, b.y);
                    __half2 h3 = __floats2half2_rn(b.z, b.w);
                    av = make_uint4(*(uint32_t*)&h0, *(uint32_t*)&h1,
                                    *(uint32_t*)&h2, *(uint32_t*)&h3);
                } else {
                    av = *(const uint4*)(g_h + (size_t)r * 128 + k0 + c8 * 8);
                }
            }
            *(uint4*)(smem + (smA - sb) + sw) = av;
            // B tiles: straight 16B copies of fp16 hi (and lo if NBT==2)
#pragma unroll
            for (int nt = 0; nt < NT; nt++) {
                size_t src = (size_t)(nt * 128 + rw) * 128 + k0 + c8 * 8;
                *(uint4*)(smem + (smBh[nt] - sb) + sw) = *(const uint4*)(Wh + src);
                if (NBT == 2)
                    *(uint4*)(smem + (smBl[nt] - sb) + sw) = *(const uint4*)(Wl + src);
            }
        }
        FENCE_ASYNC();
        __syncthreads();
        if (wid == 0) {
            if (elect_one()) {
                uint64_t ad = mk_desc(smA);
#pragma unroll
                for (int nt = 0; nt < NT; nt++) {
                    uint64_t bdh = mk_desc(smBh[nt]);
                    uint64_t bdl = (NBT == 2) ? mk_desc(smBl[nt]) : 0;
                    uint32_t dt = tmem + nt * 128;
#pragma unroll
                    for (int s = 0; s < 4; s++) {  // K=16 per f16 MMA, 4 steps = K64
                        tc_mma_f16_ss(dt, ad + s * 2, bdh + s * 2, IDESC_F16, !(c == 0 && s == 0));
                        if (NBT == 2)
                            tc_mma_f16_ss(dt, ad + s * 2, bdl + s * 2, IDESC_F16, true);
                    }
                }
                TC_COMMIT(mb);
            }
        }
    }
    mbar_wait(mb, ph);
    TC_FENCE_AFTER();

    // epilogue: warps 0..3 each cover 32 M-rows; paired tcgen05.ld, one wait per 64 cols
    if (wid < 4) {
        int r = row0 + wid * 32 + lane;
        const int NCOL = (LAYER == 1) ? 128 : 64;  // per half
        __half* dst_s = (LAYER == 1) ? g_sp1s : g_sp2s;
        __half* dst_n = (LAYER == 1) ? g_sp1nH : g_sp2nH;
#pragma unroll
        for (int half = 0; half < 2; half++) {
            __half* D = half ? dst_n : dst_s;
            int tb = half * NCOL;
#pragma unroll
            for (int off = 0; off < NCOL; off += 64) {
                uint32_t dr0[32], dr1[32];
                TC_LD_X32(dr0, tmem + tb + off);
                TC_LD_X32(dr1, tmem + tb + off + 32);
                TC_WAIT_LD();
                if (r < N_NODES) {
                    uint32_t pk[32];
#pragma unroll
                    for (int q = 0; q < 16; q++) {
                        __half2 h0 = __floats2half2_rn(__uint_as_float(dr0[2 * q]),
                                                       __uint_as_float(dr0[2 * q + 1]));
                        __half2 h1 = __floats2half2_rn(__uint_as_float(dr1[2 * q]),
                                                       __uint_as_float(dr1[2 * q + 1]));
                        pk[q] = *(uint32_t*)&h0;
                        pk[16 + q] = *(uint32_t*)&h1;
                    }
#pragma unroll
                    for (int q = 0; q < 8; q++)
                        *(uint4*)(D + (size_t)r * NCOL + off + q * 8) =
                            make_uint4(pk[q * 4], pk[q * 4 + 1], pk[q * 4 + 2], pk[q * 4 + 3]);
                }
            }
        }
        TC_FENCE_BEFORE();
    }
    __syncthreads();
    if (wid == 0) TC_DEALLOC(tmem, NT * 128);

#else  // ---------------- naive fallback (non-sm_103a pass; never runs on GB300)
    for (int e = tid; e < 128 * NT * 128; e += 256) {
        int rr = e / (NT * 128);
        int cc = e % (NT * 128);
        int r = row0 + rr;
        if (r >= N_NODES) continue;
        float s = 0.f;
        for (int k = 0; k < 128; k++) {
            float a;
            if (LAYER == 1)
                a = __half2float(__float2half_rn(A0[(size_t)r * 128 + k]));
            else
                a = __half2float(g_h[(size_t)r * 128 + k]);
            float b = __half2float(Wh[(size_t)cc * 128 + k]);
            if (NBT == 2) b += __half2float(Wl[(size_t)cc * 128 + k]);
            s += a * b;
        }
        if (LAYER == 1) {
            if (cc < 128) g_sp1s[(size_t)r * 128 + cc] = __float2half_rn(s);
            else          g_sp1nH[(size_t)r * 128 + (cc - 128)] = __float2half_rn(s);
        } else {
            if (cc < 64) g_sp2s[(size_t)r * 64 + cc] = __float2half_rn(s);
            else         g_sp2nH[(size_t)r * 64 + (cc - 64)] = __float2half_rn(s);
        }
    }
#endif
}

// ---------------- launch -----------------------------------------------------
extern "C" void kernel_launch(void* const* d_in, const int* in_sizes, int n_in,
                              void* d_out, int out_size) {
    const float* feat = (const float*)d_in[0];
    const int*   esrc = (const int*)d_in[1];
    const int*   edst = (const int*)d_in[2];
    const float* W1s  = (const float*)d_in[3];
    const float* W1n  = (const float*)d_in[4];
    const float* b1   = (const float*)d_in[5];
    const float* W2s  = (const float*)d_in[6];
    const float* W2n  = (const float*)d_in[7];
    const float* b2   = (const float*)d_in[8];
    float* out = (float*)d_out;

    static cudaStream_t s1 = nullptr;
    static cudaEvent_t e0 = nullptr, e1 = nullptr;
    if (!s1) {
        cudaStreamCreateWithFlags(&s1, cudaStreamNonBlocking);
        cudaEventCreateWithFlags(&e0, cudaEventDisableTiming);
        cudaEventCreateWithFlags(&e1, cudaEventDisableTiming);
    }

    cudaFuncSetAttribute(k_gemm<2, 1, 2>, cudaFuncAttributeMaxDynamicSharedMemorySize, GEMM1_SMEM);
    cudaFuncSetAttribute(k_gemm<1, 2, 1>, cudaFuncAttributeMaxDynamicSharedMemorySize, GEMM2_SMEM);

    const int TB = 256;

    // ---- fork: stream s1 does pack + layer-1 projection GEMM (graph-independent)
    cudaEventRecord(e0, 0);
    cudaStreamWaitEvent(s1, e0, 0);
    k_pack<<<(256 * 128 + 128 * 128 + TB - 1) / TB, TB, 0, s1>>>(W1s, W1n, W2s, W2n);
    k_gemm<2, 1, 2><<<TOT_TILES, 256, GEMM1_SMEM, s1>>>(feat);
    cudaEventRecord(e1, s1);

    // ---- default stream: CSR build
    k_zero_deg<<<(N_NODES + TB - 1) / TB, TB>>>();
    k_hist<<<(N_EDGES + TB - 1) / TB, TB>>>(edst);
    k_scan1<<<(N_NODES + 1023) / 1024, 1024>>>();
    k_scan3<<<(N_NODES + TB - 1) / TB, TB>>>();
    k_fill<<<(N_EDGES + TB - 1) / TB, TB>>>(esrc, edst);

    // ---- join
    cudaStreamWaitEvent(0, e1, 0);

    // layer 1 aggregate (+self+bias+relu), layer 2 projection, layer 2 aggregate
    k_agg1<<<(N_NODES * 32 + TB - 1) / TB, TB>>>(b1);
    k_gemm<1, 2, 1><<<TOT_TILES, 256, GEMM2_SMEM>>>(nullptr);
    k_agg2<<<(N_NODES * 32 + TB - 1) / TB, TB>>>(b2, out);
}